// round 13
// baseline (speedup 1.0000x reference)
#include <cuda_runtime.h>
#include <cuda_fp16.h>
#include <math.h>

#define NN 30000
#define EE 480000
#define GG 64
#define HF 64
#define HEADS 8
#define MLPD 256

// ---------------- device scratch ----------------
__device__ float  g_h[NN * HF];
__device__ __half g_feat1[(size_t)NN * 512];
__device__ __half g_res1[(size_t)NN * 512];
__device__ float  g_el1[NN * HEADS];
__device__ float  g_er1[NN * HEADS];
__device__ float  g_h1[NN * HF];
__device__ __half g_feat2[NN * HF];
__device__ float  g_el2[NN];
__device__ float  g_er2[NN];
__device__ int    g_deg[NN];
__device__ int    g_off[NN];
__device__ int    g_cur[NN];
__device__ int    g_bsum[256];
__device__ int    g_srcs[EE];
__device__ float  g_p0[GG * HF];
__device__ float  g_p1[GG * HF];
__device__ float  g_p2[GG * HF];

// ---------------- helpers ----------------
__device__ __forceinline__ unsigned f2tf(float f) {
    unsigned r;
    asm("cvt.rna.tf32.f32 %0, %1;" : "=r"(r) : "f"(f));
    return r;
}

__device__ __forceinline__ void mma_tf32(float* c, unsigned a0, unsigned a1,
                                         unsigned a2, unsigned a3,
                                         unsigned b0, unsigned b1) {
    asm("mma.sync.aligned.m16n8k8.row.col.f32.tf32.tf32.f32 "
        "{%0,%1,%2,%3},{%4,%5,%6,%7},{%8,%9},{%0,%1,%2,%3};"
        : "+f"(c[0]), "+f"(c[1]), "+f"(c[2]), "+f"(c[3])
        : "r"(a0), "r"(a1), "r"(a2), "r"(a3), "r"(b0), "r"(b1));
}

__device__ __forceinline__ float elu_fast(float x) {
    return x > 0.f ? x : (__expf(x) - 1.f);
}

// ---------------- init ----------------
__global__ void init_kernel(int* deg, float* p0, float* p1, float* p2, int n) {
    int i = blockIdx.x * blockDim.x + threadIdx.x;
    if (i < n) deg[i] = 0;
    if (i < GG * HF) { p0[i] = 0.f; p1[i] = 0.f; p2[i] = 0.f; }
}

// ---------------- CSR build ----------------
__global__ void hist_kernel(const int* __restrict__ dst, int* __restrict__ deg, int E) {
    int e = blockIdx.x * blockDim.x + threadIdx.x;
    if (e < E) atomicAdd(&deg[dst[e]], 1);
}

__global__ void scan1_kernel(const int* __restrict__ deg, int* __restrict__ off,
                             int* __restrict__ bsum, int n) {
    __shared__ int sm[256];
    int t = threadIdx.x;
    int i = blockIdx.x * 256 + t;
    int v = (i < n) ? deg[i] : 0;
    sm[t] = v;
    __syncthreads();
#pragma unroll
    for (int o = 1; o < 256; o <<= 1) {
        int x = (t >= o) ? sm[t - o] : 0;
        __syncthreads();
        sm[t] += x;
        __syncthreads();
    }
    if (i < n) off[i] = sm[t] - v;
    if (t == 255) bsum[blockIdx.x] = sm[255];
}

__global__ void scan2_kernel(const int* __restrict__ bsum, int* __restrict__ off,
                             int* __restrict__ cur, int n, int nblocks) {
    __shared__ int sb[256];
    int t = threadIdx.x;
    sb[t] = (t < nblocks) ? bsum[t] : 0;
    __syncthreads();
#pragma unroll
    for (int o = 1; o < 256; o <<= 1) {
        int x = (t >= o) ? sb[t - o] : 0;
        __syncthreads();
        sb[t] += x;
        __syncthreads();
    }
    int b = blockIdx.x;
    int base = (b > 0) ? sb[b - 1] : 0;
    int i = b * 256 + t;
    if (i < n) {
        int o = off[i] + base;
        off[i] = o;
        cur[i] = o;
    }
}

__global__ void scatter_kernel(const int* __restrict__ src, const int* __restrict__ dst,
                               int* __restrict__ cur, int* __restrict__ srcs, int E) {
    int e = blockIdx.x * blockDim.x + threadIdx.x;
    if (e < E) {
        int d = dst[e];
        int pos = atomicAdd(&cur[d], 1);
        srcs[pos] = src[e];
    }
}

// ---------------- tf32 tensor-core GEMMs ----------------
#define AS_LD 72
#define WS_LD 136
#define GEMM_SMEM ((128 * AS_LD + 64 * WS_LD) * 4)

__device__ __forceinline__ void load_A_tile(const float* __restrict__ A, unsigned* As,
                                            int r0, int M, int tid) {
#pragma unroll
    for (int i = 0; i < 8; i++) {
        int f = tid + i * 256;
        int row = f >> 4;
        int c4 = (f & 15) * 4;
        float4 v = make_float4(0.f, 0.f, 0.f, 0.f);
        if (r0 + row < M) v = *(const float4*)(A + (size_t)(r0 + row) * 64 + c4);
        int kb = c4 >> 3;
        int basep = row * AS_LD + kb * 8 + ((c4 & 4) ? 1 : 0);
        As[basep + 0] = f2tf(v.x);
        As[basep + 2] = f2tf(v.y);
        As[basep + 4] = f2tf(v.z);
        As[basep + 6] = f2tf(v.w);
    }
}

__device__ __forceinline__ void load_W_tile(const float* __restrict__ W, unsigned* Ws,
                                            int ldw, int NC, int c0, int tid) {
#pragma unroll
    for (int i = 0; i < 8; i++) {
        int f = tid + i * 256;
        int row = f >> 5;
        int c4 = (f & 31) * 4;
        float4 v = make_float4(0.f, 0.f, 0.f, 0.f);
        if (c0 + c4 < NC) v = *(const float4*)(W + (size_t)row * ldw + c0 + c4);
        Ws[row * WS_LD + c4 + 0] = f2tf(v.x);
        Ws[row * WS_LD + c4 + 1] = f2tf(v.y);
        Ws[row * WS_LD + c4 + 2] = f2tf(v.z);
        Ws[row * WS_LD + c4 + 3] = f2tf(v.w);
    }
}

__device__ __forceinline__ void gemm_mainloop(const unsigned* As, const unsigned* Ws,
                                              float acc[2][8][4], int wm, int wn,
                                              int g, int tg) {
#pragma unroll
    for (int kb = 0; kb < 8; kb++) {
        unsigned a[2][4];
#pragma unroll
        for (int mt = 0; mt < 2; mt++) {
            int rb = wm * 32 + mt * 16;
            uint2 pa = *(const uint2*)&As[(rb + g) * AS_LD + kb * 8 + tg * 2];
            uint2 pb = *(const uint2*)&As[(rb + 8 + g) * AS_LD + kb * 8 + tg * 2];
            a[mt][0] = pa.x; a[mt][2] = pa.y;
            a[mt][1] = pb.x; a[mt][3] = pb.y;
        }
        int kk = kb * 8;
#pragma unroll
        for (int nt = 0; nt < 8; nt++) {
            int cb = wn * 64 + nt * 8 + g;
            unsigned b0 = Ws[(kk + tg) * WS_LD + cb];
            unsigned b1 = Ws[(kk + tg + 4) * WS_LD + cb];
            mma_tf32(acc[0][nt], a[0][0], a[0][1], a[0][2], a[0][3], b0, b1);
            mma_tf32(acc[1][nt], a[1][0], a[1][1], a[1][2], a[1][3], b0, b1);
        }
    }
}

__global__ void gemm_tf32(const float* __restrict__ A, const float* __restrict__ W,
                          int ldw, int NC, float* __restrict__ C, __half* __restrict__ Ch,
                          int ldc, int M, const float* __restrict__ bias,
                          const int* __restrict__ gid, float* __restrict__ pool) {
    extern __shared__ unsigned smem_u[];
    unsigned* As = smem_u;
    unsigned* Ws = smem_u + 128 * AS_LD;
    int tid = threadIdx.x;
    int warp = tid >> 5, lane = tid & 31;
    int g = lane >> 2, tg = lane & 3;
    int wm = warp & 3, wn = warp >> 2;
    int r0 = blockIdx.y * 128;
    int c0 = blockIdx.x * 128;

    load_A_tile(A, As, r0, M, tid);
    load_W_tile(W, Ws, ldw, NC, c0, tid);
    __syncthreads();

    float acc[2][8][4];
#pragma unroll
    for (int mt = 0; mt < 2; mt++)
#pragma unroll
        for (int nt = 0; nt < 8; nt++)
#pragma unroll
            for (int q = 0; q < 4; q++) acc[mt][nt][q] = 0.f;

    gemm_mainloop(As, Ws, acc, wm, wn, g, tg);

#pragma unroll
    for (int mt = 0; mt < 2; mt++) {
#pragma unroll
        for (int nt = 0; nt < 8; nt++) {
            int col = c0 + wn * 64 + nt * 8 + tg * 2;
            if (col >= NC) continue;
            float bv0 = 0.f, bv1 = 0.f;
            if (bias) { bv0 = bias[col]; bv1 = bias[col + 1]; }
            int rowA = r0 + wm * 32 + mt * 16 + g;
#pragma unroll
            for (int half = 0; half < 2; half++) {
                int row = rowA + half * 8;
                if (row >= M) continue;
                float v0 = acc[mt][nt][half * 2 + 0] + bv0;
                float v1 = acc[mt][nt][half * 2 + 1] + bv1;
                if (Ch) {
                    *(__half2*)(Ch + (size_t)row * ldc + col) = __floats2half2_rn(v0, v1);
                } else {
                    *(float2*)(C + (size_t)row * ldc + col) = make_float2(v0, v1);
                    if (pool) {
                        int gi = gid[row];
                        atomicAdd(&pool[gi * HF + col], v0);
                        atomicAdd(&pool[gi * HF + col + 1], v1);
                    }
                }
            }
        }
    }
}

__global__ void gemm_fr1(const float* __restrict__ A, const float* __restrict__ Wf,
                         const float* __restrict__ Wr, __half* __restrict__ feat1,
                         __half* __restrict__ res1, int M) {
    extern __shared__ unsigned smem_u[];
    unsigned* As = smem_u;
    unsigned* Ws = smem_u + 128 * AS_LD;
    int tid = threadIdx.x;
    int warp = tid >> 5, lane = tid & 31;
    int g = lane >> 2, tg = lane & 3;
    int wm = warp & 3, wn = warp >> 2;
    int r0 = blockIdx.y * 128;
    int bx = blockIdx.x;
    int c0 = (bx & 3) * 128;
    const float* W = (bx >= 4) ? Wr : Wf;
    __half* Out = (bx >= 4) ? res1 : feat1;

    load_A_tile(A, As, r0, M, tid);
    load_W_tile(W, Ws, 512, 512, c0, tid);
    __syncthreads();

    float acc[2][8][4];
#pragma unroll
    for (int mt = 0; mt < 2; mt++)
#pragma unroll
        for (int nt = 0; nt < 8; nt++)
#pragma unroll
            for (int q = 0; q < 4; q++) acc[mt][nt][q] = 0.f;

    gemm_mainloop(As, Ws, acc, wm, wn, g, tg);

#pragma unroll
    for (int mt = 0; mt < 2; mt++) {
#pragma unroll
        for (int nt = 0; nt < 8; nt++) {
            int col = c0 + wn * 64 + nt * 8 + tg * 2;
            int rowA = r0 + wm * 32 + mt * 16 + g;
#pragma unroll
            for (int half = 0; half < 2; half++) {
                int row = rowA + half * 8;
                if (row >= M) continue;
                float v0 = acc[mt][nt][half * 2 + 0];
                float v1 = acc[mt][nt][half * 2 + 1];
                *(__half2*)(Out + (size_t)row * 512 + col) = __floats2half2_rn(v0, v1);
            }
        }
    }
}

// ---------------- el/er for layer 1 ----------------
__global__ void elr1_kernel(const __half* __restrict__ feat1, const float* __restrict__ al,
                            const float* __restrict__ ar, float* __restrict__ el,
                            float* __restrict__ er, int M) {
    __shared__ float sal[512], sar[512];
    int tid = threadIdx.x;
    for (int i = tid; i < 512; i += 256) { sal[i] = al[i]; sar[i] = ar[i]; }
    __syncthreads();
    int warp = tid >> 5, lane = tid & 31;
    int n = blockIdx.x * 8 + warp;
    if (n >= M) return;
    const __half* fp = feat1 + (size_t)n * 512 + lane * 16;
    uint4 u0 = *(const uint4*)fp;
    uint4 u1 = *(const uint4*)(fp + 8);
    const __half2* h0 = (const __half2*)&u0;
    const __half2* h1 = (const __half2*)&u1;
    float pl = 0.f, pr = 0.f;
#pragma unroll
    for (int j = 0; j < 4; j++) {
        float2 f = __half22float2(h0[j]);
        pl += f.x * sal[lane * 16 + 2 * j] + f.y * sal[lane * 16 + 2 * j + 1];
        pr += f.x * sar[lane * 16 + 2 * j] + f.y * sar[lane * 16 + 2 * j + 1];
    }
#pragma unroll
    for (int j = 0; j < 4; j++) {
        float2 f = __half22float2(h1[j]);
        pl += f.x * sal[lane * 16 + 8 + 2 * j] + f.y * sal[lane * 16 + 8 + 2 * j + 1];
        pr += f.x * sar[lane * 16 + 8 + 2 * j] + f.y * sar[lane * 16 + 8 + 2 * j + 1];
    }
    pl += __shfl_xor_sync(0xffffffffu, pl, 1);
    pl += __shfl_xor_sync(0xffffffffu, pl, 2);
    pr += __shfl_xor_sync(0xffffffffu, pr, 1);
    pr += __shfl_xor_sync(0xffffffffu, pr, 2);
    if ((lane & 3) == 0) {
        int h = lane >> 2;
        el[n * HEADS + h] = pl;
        er[n * HEADS + h] = pr;
    }
}

// ---------------- layer-1 aggregation: 4 warps per node (2 heads/warp) -------------
__global__ void agg1_kernel(const __half* __restrict__ feat1, const __half* __restrict__ res1,
                            const float* __restrict__ el, const float* __restrict__ er,
                            const int* __restrict__ off, const int* __restrict__ degv,
                            const int* __restrict__ srcs, const float* __restrict__ b1,
                            const int* __restrict__ gid, float* __restrict__ h1,
                            float* __restrict__ pool, int M) {
    __shared__ float sy[2][512];
    int warp = threadIdx.x >> 5, lane = threadIdx.x & 31;
    int nid = warp >> 2;
    int wn = warp & 3;
    int n = blockIdx.x * 2 + nid;
    bool active = (n < M);
    int hh = wn * 2 + (lane >> 4);
    int p = lane & 15;
    int col = hh * 64 + p * 4;

    int start = 0, deg = 0;
    float erh = 0.f;
    if (active) {
        start = off[n];
        deg = degv[n];
        erh = er[n * HEADS + hh];
    }

    float m = -1e30f, den = 0.f;
    float acc[4] = {0.f, 0.f, 0.f, 0.f};

    for (int k0 = 0; k0 < deg; k0 += 4) {
        int cnt = deg - k0;
        int s4[4];
        s4[0] = srcs[start + k0];
#pragma unroll
        for (int i = 1; i < 4; i++)
            s4[i] = (i < cnt) ? srcs[start + k0 + i] : s4[0];
        float e4[4];
#pragma unroll
        for (int i = 0; i < 4; i++) e4[i] = el[s4[i] * HEADS + hh];
        uint2 f4[4];
#pragma unroll
        for (int i = 0; i < 4; i++)
            f4[i] = *(const uint2*)(feat1 + (size_t)s4[i] * 512 + col);
        float bm = -1e30f;
#pragma unroll
        for (int i = 0; i < 4; i++) {
            float e = e4[i] + erh;
            e = e > 0.f ? e : 0.2f * e;
            e4[i] = (i < cnt) ? e : -1e30f;
            bm = fmaxf(bm, e4[i]);
        }
        if (bm > m) {
            float c = __expf(m - bm);
            den *= c;
#pragma unroll
            for (int q = 0; q < 4; q++) acc[q] *= c;
            m = bm;
        }
#pragma unroll
        for (int i = 0; i < 4; i++) {
            float pw = __expf(e4[i] - m);
            den += pw;
            __half2 lo = *(__half2*)&f4[i].x;
            __half2 hi = *(__half2*)&f4[i].y;
            float2 v0 = __half22float2(lo);
            float2 v1 = __half22float2(hi);
            acc[0] += pw * v0.x;
            acc[1] += pw * v0.y;
            acc[2] += pw * v1.x;
            acc[3] += pw * v1.y;
        }
    }
    float inv = (deg > 0) ? (1.f / den) : 0.f;

    float x[4] = {0.f, 0.f, 0.f, 0.f};
    float s1 = 0.f, s2 = 0.f;
    if (active) {
        uint2 rv = *(const uint2*)(res1 + (size_t)n * 512 + col);
        __half2 rlo = *(__half2*)&rv.x;
        __half2 rhi = *(__half2*)&rv.y;
        float2 r0 = __half22float2(rlo);
        float2 r1 = __half22float2(rhi);
        float rr[4] = {r0.x, r0.y, r1.x, r1.y};
        float4 bv = *(const float4*)(b1 + col);
        float bb[4] = {bv.x, bv.y, bv.z, bv.w};
#pragma unroll
        for (int q = 0; q < 4; q++) {
            float val = acc[q] * inv + rr[q] + bb[q];
            val = elu_fast(val);
            x[q] = val;
            s1 += val;
            s2 += val * val;
        }
    }
#pragma unroll
    for (int o = 1; o <= 8; o <<= 1) {
        s1 += __shfl_xor_sync(0xffffffffu, s1, o);
        s2 += __shfl_xor_sync(0xffffffffu, s2, o);
    }
    float mu = s1 * (1.f / 64.f);
    float var = s2 * (1.f / 64.f) - mu * mu;
    float rs = rsqrtf(var + 1e-5f);
    if (active) {
#pragma unroll
        for (int q = 0; q < 4; q++)
            sy[nid][col + q] = (x[q] - mu) * rs;
    }
    __syncthreads();
    if (wn == 0 && active) {
        int d0 = lane * 2;
        float y0 = 0.f, y1 = 0.f;
#pragma unroll
        for (int hq = 0; hq < 8; hq++) {
            y0 += sy[nid][hq * 64 + d0];
            y1 += sy[nid][hq * 64 + d0 + 1];
        }
        y0 *= 0.125f;
        y1 *= 0.125f;
        int g = gid[n];
        *(float2*)(h1 + (size_t)n * HF + d0) = make_float2(y0, y1);
        atomicAdd(&pool[g * HF + d0 + 0], y0);
        atomicAdd(&pool[g * HF + d0 + 1], y1);
    }
}

// ---------------- el/er for layer 2 (fp16 feat2) ----------------
__global__ void elr2_kernel(const __half* __restrict__ feat2, const float* __restrict__ al,
                            const float* __restrict__ ar, float* __restrict__ el,
                            float* __restrict__ er, int M) {
    int warp = threadIdx.x >> 5, lane = threadIdx.x & 31;
    int n = blockIdx.x * 8 + warp;
    if (n >= M) return;
    int d0 = lane * 2;
    float2 f = __half22float2(*(const __half2*)(feat2 + (size_t)n * HF + d0));
    float pl = f.x * al[d0] + f.y * al[d0 + 1];
    float pr = f.x * ar[d0] + f.y * ar[d0 + 1];
#pragma unroll
    for (int o = 16; o > 0; o >>= 1) {
        pl += __shfl_xor_sync(0xffffffffu, pl, o);
        pr += __shfl_xor_sync(0xffffffffu, pr, o);
    }
    if (lane == 0) { el[n] = pl; er[n] = pr; }
}

// ---------------- layer-2 aggregation: 4 warps per node split edges ---------------
// block = 256 thr = 8 warps = 2 nodes x 4 warps. Warp wq handles edge chunk wq of 4.
// Each lane covers dims d0 = lane*2. Partial softmax states merged via smem.
__global__ void agg2_kernel(const __half* __restrict__ feat2, const float* __restrict__ el,
                            const float* __restrict__ er, const int* __restrict__ off,
                            const int* __restrict__ degv, const int* __restrict__ srcs,
                            const float* __restrict__ h1, const float* __restrict__ b2,
                            const int* __restrict__ gid, float* __restrict__ pool, int M) {
    __shared__ float sm_m[2][4], sm_den[2][4];
    __shared__ float sm_acc[2][4][64];
    int warp = threadIdx.x >> 5, lane = threadIdx.x & 31;
    int nid = warp >> 2;
    int wq = warp & 3;
    int n = blockIdx.x * 2 + nid;
    bool active = (n < M);
    int d0 = lane * 2;

    int start = 0, deg = 0;
    float ern = 0.f;
    if (active) {
        start = off[n];
        deg = degv[n];
        ern = er[n];
    }
    int per = (deg + 3) >> 2;
    int kb = wq * per;
    int ke = min(deg, kb + per);

    float m = -1e30f, den = 0.f, a0 = 0.f, a1 = 0.f;

    for (int k0 = kb; k0 < ke; k0 += 4) {
        int cnt = ke - k0;
        int s4[4];
        s4[0] = srcs[start + k0];
#pragma unroll
        for (int i = 1; i < 4; i++)
            s4[i] = (i < cnt) ? srcs[start + k0 + i] : s4[0];
        float e4[4];
#pragma unroll
        for (int i = 0; i < 4; i++) e4[i] = el[s4[i]];
        unsigned f4[4];
#pragma unroll
        for (int i = 0; i < 4; i++)
            f4[i] = *(const unsigned*)(feat2 + (size_t)s4[i] * HF + d0);
        float bm = -1e30f;
#pragma unroll
        for (int i = 0; i < 4; i++) {
            float e = e4[i] + ern;
            e = e > 0.f ? e : 0.2f * e;
            e4[i] = (i < cnt) ? e : -1e30f;
            bm = fmaxf(bm, e4[i]);
        }
        if (bm > m) {
            float c = __expf(m - bm);
            den *= c; a0 *= c; a1 *= c;
            m = bm;
        }
#pragma unroll
        for (int i = 0; i < 4; i++) {
            float pw = __expf(e4[i] - m);
            den += pw;
            float2 v = __half22float2(*(const __half2*)&f4[i]);
            a0 += pw * v.x;
            a1 += pw * v.y;
        }
    }

    // publish partial state
    if (lane == 0) { sm_m[nid][wq] = m; sm_den[nid][wq] = den; }
    sm_acc[nid][wq][d0] = a0;
    sm_acc[nid][wq][d0 + 1] = a1;
    __syncthreads();

    // warp 0 of each node combines + epilogue
    if (wq == 0 && active) {
        float m0 = sm_m[nid][0], m1 = sm_m[nid][1];
        float m2 = sm_m[nid][2], m3 = sm_m[nid][3];
        float Mx = fmaxf(fmaxf(m0, m1), fmaxf(m2, m3));
        float w0 = (m0 > -1e29f) ? __expf(m0 - Mx) : 0.f;
        float w1 = (m1 > -1e29f) ? __expf(m1 - Mx) : 0.f;
        float w2 = (m2 > -1e29f) ? __expf(m2 - Mx) : 0.f;
        float w3 = (m3 > -1e29f) ? __expf(m3 - Mx) : 0.f;
        float D = sm_den[nid][0] * w0 + sm_den[nid][1] * w1 +
                  sm_den[nid][2] * w2 + sm_den[nid][3] * w3;
        float inv = (deg > 0) ? (1.f / D) : 0.f;
        float A0 = sm_acc[nid][0][d0] * w0 + sm_acc[nid][1][d0] * w1 +
                   sm_acc[nid][2][d0] * w2 + sm_acc[nid][3][d0] * w3;
        float A1 = sm_acc[nid][0][d0 + 1] * w0 + sm_acc[nid][1][d0 + 1] * w1 +
                   sm_acc[nid][2][d0 + 1] * w2 + sm_acc[nid][3][d0 + 1] * w3;

        float2 hv = *(const float2*)(h1 + (size_t)n * HF + d0);
        float x0 = elu_fast(A0 * inv + hv.x + b2[d0]);
        float x1 = elu_fast(A1 * inv + hv.y + b2[d0 + 1]);
        float s1 = x0 + x1;
        float s2 = x0 * x0 + x1 * x1;
#pragma unroll
        for (int o = 16; o > 0; o >>= 1) {
            s1 += __shfl_xor_sync(0xffffffffu, s1, o);
            s2 += __shfl_xor_sync(0xffffffffu, s2, o);
        }
        float mu = s1 * (1.f / 64.f);
        float var = s2 * (1.f / 64.f) - mu * mu;
        float rs = rsqrtf(var + 1e-5f);
        float y0 = (x0 - mu) * rs;
        float y1 = (x1 - mu) * rs;
        int g = gid[n];
        atomicAdd(&pool[g * HF + d0 + 0], y0);
        atomicAdd(&pool[g * HF + d0 + 1], y1);
    }
}

// ---------------- fused graph head ----------------
__global__ void head_kernel(const float* __restrict__ p0, const float* __restrict__ p1,
                            const float* __restrict__ p2, const float* __restrict__ gW1,
                            const float* __restrict__ gb1, const float* __restrict__ gW2,
                            const float* __restrict__ gb2, const float* __restrict__ mW0,
                            const float* __restrict__ mb0, const float* __restrict__ mW1,
                            const float* __restrict__ mb1, const float* __restrict__ mW2,
                            const float* __restrict__ mb2, float* __restrict__ out) {
    __shared__ float a1[64], a2[64], hg[64], t0s[256], t1s[256];
    int g = blockIdx.x, t = threadIdx.x;
    if (t < 64) { a1[t] = p1[g * 64 + t]; a2[t] = p2[g * 64 + t]; }
    __syncthreads();
    if (t < 64) {
        float s1 = gb1[t], s2 = gb2[t];
        for (int k = 0; k < 64; k++) {
            s1 += a1[k] * gW1[k * 64 + t];
            s2 += a2[k] * gW2[k * 64 + t];
        }
        s1 = s1 > 0.f ? s1 : 0.01f * s1;
        s2 = s2 > 0.f ? s2 : 0.01f * s2;
        hg[t] = p0[g * 64 + t] + s1 + s2;
    }
    __syncthreads();
    float acc = mb0[t];
    for (int k = 0; k < 64; k++) acc += hg[k] * mW0[k * 256 + t];
    t0s[t] = fmaxf(acc, 0.f);
    __syncthreads();
    acc = mb1[t];
    for (int k = 0; k < 256; k++) acc += t0s[k] * mW1[k * 256 + t];
    t1s[t] = fmaxf(acc, 0.f);
    __syncthreads();
    acc = mb2[t];
    for (int k = 0; k < 256; k++) acc += t1s[k] * mW2[k * 256 + t];
    out[g * 256 + t] = acc;
}

// ---------------- launch ----------------
extern "C" void kernel_launch(void* const* d_in, const int* in_sizes, int n_in,
                              void* d_out, int out_size) {
    const float* X     = (const float*)d_in[0];
    const int*   src   = (const int*)d_in[1];
    const int*   dst   = (const int*)d_in[2];
    const int*   gid   = (const int*)d_in[3];
    const float* projW = (const float*)d_in[4];
    const float* projb = (const float*)d_in[5];
    const float* fcW1  = (const float*)d_in[6];
    const float* al1   = (const float*)d_in[7];
    const float* ar1   = (const float*)d_in[8];
    const float* resW1 = (const float*)d_in[9];
    const float* b1    = (const float*)d_in[10];
    const float* fcW2  = (const float*)d_in[11];
    const float* al2   = (const float*)d_in[12];
    const float* ar2   = (const float*)d_in[13];
    const float* b2    = (const float*)d_in[14];
    const float* gW1   = (const float*)d_in[15];
    const float* gb1   = (const float*)d_in[16];
    const float* gW2   = (const float*)d_in[17];
    const float* gb2   = (const float*)d_in[18];
    const float* mW0   = (const float*)d_in[19];
    const float* mb0   = (const float*)d_in[20];
    const float* mW1   = (const float*)d_in[21];
    const float* mb1   = (const float*)d_in[22];
    const float* mW2   = (const float*)d_in[23];
    const float* mb2   = (const float*)d_in[24];

    int M = in_sizes[0] / HF;
    int E = in_sizes[1];

    float *h, *el1, *er1, *h1, *el2, *er2;
    float *p0, *p1, *p2;
    __half *feat1, *res1, *feat2;
    int *deg, *off, *cur, *bsum, *srcs;
    cudaGetSymbolAddress((void**)&h, g_h);
    cudaGetSymbolAddress((void**)&feat1, g_feat1);
    cudaGetSymbolAddress((void**)&res1, g_res1);
    cudaGetSymbolAddress((void**)&el1, g_el1);
    cudaGetSymbolAddress((void**)&er1, g_er1);
    cudaGetSymbolAddress((void**)&h1, g_h1);
    cudaGetSymbolAddress((void**)&feat2, g_feat2);
    cudaGetSymbolAddress((void**)&el2, g_el2);
    cudaGetSymbolAddress((void**)&er2, g_er2);
    cudaGetSymbolAddress((void**)&deg, g_deg);
    cudaGetSymbolAddress((void**)&off, g_off);
    cudaGetSymbolAddress((void**)&cur, g_cur);
    cudaGetSymbolAddress((void**)&bsum, g_bsum);
    cudaGetSymbolAddress((void**)&srcs, g_srcs);
    cudaGetSymbolAddress((void**)&p0, g_p0);
    cudaGetSymbolAddress((void**)&p1, g_p1);
    cudaGetSymbolAddress((void**)&p2, g_p2);

    static int smem_set = 0;
    if (!smem_set) {
        cudaFuncSetAttribute(gemm_tf32, cudaFuncAttributeMaxDynamicSharedMemorySize,
                             GEMM_SMEM);
        cudaFuncSetAttribute(gemm_fr1, cudaFuncAttributeMaxDynamicSharedMemorySize,
                             GEMM_SMEM);
        smem_set = 1;
    }

    int nwb = (M + 7) / 8;
    int nwb2 = (M + 1) / 2;          // 2 nodes per block
    int rowTiles = (M + 127) / 128;
    int scanBlocks = (M + 255) / 256;

    init_kernel<<<(M + 255) / 256, 256>>>(deg, p0, p1, p2, M);                        // 1
    hist_kernel<<<(E + 255) / 256, 256>>>(dst, deg, E);                               // 2
    gemm_tf32<<<dim3(1, rowTiles), 256, GEMM_SMEM>>>(X, projW, HF, HF, h, nullptr,
                                                     HF, M, projb, gid, p0);          // 3
    gemm_fr1<<<dim3(8, rowTiles), 256, GEMM_SMEM>>>(h, fcW1, resW1, feat1, res1, M);  // 4 <- capture
    scan1_kernel<<<scanBlocks, 256>>>(deg, off, bsum, M);                             // 5
    scan2_kernel<<<scanBlocks, 256>>>(bsum, off, cur, M, scanBlocks);                 // 6
    scatter_kernel<<<(E + 255) / 256, 256>>>(src, dst, cur, srcs, E);                 // 7
    elr1_kernel<<<nwb, 256>>>(feat1, al1, ar1, el1, er1, M);                          // 8
    agg1_kernel<<<nwb2, 256>>>(feat1, res1, el1, er1, off, deg, srcs, b1, gid,
                               h1, p1, M);                                            // 9
    gemm_tf32<<<dim3(1, rowTiles), 256, GEMM_SMEM>>>(h1, fcW2, HF, HF, nullptr,
                                                     feat2, HF, M, nullptr, nullptr,
                                                     nullptr);                        // 10
    elr2_kernel<<<nwb, 256>>>(feat2, al2, ar2, el2, er2, M);                          // 11
    agg2_kernel<<<nwb2, 256>>>(feat2, el2, er2, off, deg, srcs, h1, b2, gid, p2, M);  // 12
    head_kernel<<<GG, MLPD>>>(p0, p1, p2, gW1, gb1, gW2, gb2, mW0, mb0, mW1, mb1,
                              mW2, mb2, (float*)d_out);                               // 13
}

// round 14
// speedup vs baseline: 1.0245x; 1.0245x over previous
#include <cuda_runtime.h>
#include <cuda_fp16.h>
#include <math.h>

#define NN 30000
#define EE 480000
#define GG 64
#define HF 64
#define HEADS 8
#define MLPD 256

// ---------------- device scratch ----------------
__device__ float  g_h[NN * HF];
__device__ __half g_feat1[(size_t)NN * 512];
__device__ __half g_res1[(size_t)NN * 512];
__device__ float  g_el1[NN * HEADS];
__device__ float  g_er1[NN * HEADS];
__device__ float  g_h1[NN * HF];
__device__ __half g_feat2[NN * HF];
__device__ float  g_el2[NN];
__device__ float  g_er2[NN];
__device__ int    g_deg[NN];
__device__ int    g_off[NN];
__device__ int    g_cur[NN];
__device__ int    g_bsum[256];
__device__ int    g_srcs[EE];
__device__ float  g_p0[GG * HF];
__device__ float  g_p1[GG * HF];
__device__ float  g_p2[GG * HF];

// ---------------- helpers ----------------
__device__ __forceinline__ unsigned f2tf(float f) {
    unsigned r;
    asm("cvt.rna.tf32.f32 %0, %1;" : "=r"(r) : "f"(f));
    return r;
}

__device__ __forceinline__ void mma_tf32(float* c, unsigned a0, unsigned a1,
                                         unsigned a2, unsigned a3,
                                         unsigned b0, unsigned b1) {
    asm("mma.sync.aligned.m16n8k8.row.col.f32.tf32.tf32.f32 "
        "{%0,%1,%2,%3},{%4,%5,%6,%7},{%8,%9},{%0,%1,%2,%3};"
        : "+f"(c[0]), "+f"(c[1]), "+f"(c[2]), "+f"(c[3])
        : "r"(a0), "r"(a1), "r"(a2), "r"(a3), "r"(b0), "r"(b1));
}

__device__ __forceinline__ float elu_fast(float x) {
    return x > 0.f ? x : (__expf(x) - 1.f);
}

// ---------------- init ----------------
__global__ void init_kernel(int* deg, float* p0, float* p1, float* p2, int n) {
    int i = blockIdx.x * blockDim.x + threadIdx.x;
    if (i < n) deg[i] = 0;
    if (i < GG * HF) { p0[i] = 0.f; p1[i] = 0.f; p2[i] = 0.f; }
}

// ---------------- CSR build ----------------
__global__ void hist_kernel(const int* __restrict__ dst, int* __restrict__ deg, int E) {
    int e = blockIdx.x * blockDim.x + threadIdx.x;
    if (e < E) atomicAdd(&deg[dst[e]], 1);
}

__global__ void scan1_kernel(const int* __restrict__ deg, int* __restrict__ off,
                             int* __restrict__ bsum, int n) {
    __shared__ int sm[256];
    int t = threadIdx.x;
    int i = blockIdx.x * 256 + t;
    int v = (i < n) ? deg[i] : 0;
    sm[t] = v;
    __syncthreads();
#pragma unroll
    for (int o = 1; o < 256; o <<= 1) {
        int x = (t >= o) ? sm[t - o] : 0;
        __syncthreads();
        sm[t] += x;
        __syncthreads();
    }
    if (i < n) off[i] = sm[t] - v;
    if (t == 255) bsum[blockIdx.x] = sm[255];
}

__global__ void scan2_kernel(const int* __restrict__ bsum, int* __restrict__ off,
                             int* __restrict__ cur, int n, int nblocks) {
    __shared__ int sb[256];
    int t = threadIdx.x;
    sb[t] = (t < nblocks) ? bsum[t] : 0;
    __syncthreads();
#pragma unroll
    for (int o = 1; o < 256; o <<= 1) {
        int x = (t >= o) ? sb[t - o] : 0;
        __syncthreads();
        sb[t] += x;
        __syncthreads();
    }
    int b = blockIdx.x;
    int base = (b > 0) ? sb[b - 1] : 0;
    int i = b * 256 + t;
    if (i < n) {
        int o = off[i] + base;
        off[i] = o;
        cur[i] = o;
    }
}

__global__ void scatter_kernel(const int* __restrict__ src, const int* __restrict__ dst,
                               int* __restrict__ cur, int* __restrict__ srcs, int E) {
    int e = blockIdx.x * blockDim.x + threadIdx.x;
    if (e < E) {
        int d = dst[e];
        int pos = atomicAdd(&cur[d], 1);
        srcs[pos] = src[e];
    }
}

// ---------------- tf32 tensor-core GEMMs ----------------
// A: fragment-major, pairs (k, k+4) adjacent; AS_LD=72.
// B: pair-major — for (kb, tg), W[kk+tg][cb] and W[kk+tg+4][cb] adjacent -> LDS.64.
//    Wp row = (kb*4 + tg), pitch WP_LD unsigned; element at cb*2 + {0,1}.
#define AS_LD 72
#define WP_LD 264
#define GEMM_SMEM ((128 * AS_LD + 32 * WP_LD) * 4)

__device__ __forceinline__ void load_A_tile(const float* __restrict__ A, unsigned* As,
                                            int r0, int M, int tid) {
#pragma unroll
    for (int i = 0; i < 8; i++) {
        int f = tid + i * 256;
        int row = f >> 4;
        int c4 = (f & 15) * 4;
        float4 v = make_float4(0.f, 0.f, 0.f, 0.f);
        if (r0 + row < M) v = *(const float4*)(A + (size_t)(r0 + row) * 64 + c4);
        int kb = c4 >> 3;
        int basep = row * AS_LD + kb * 8 + ((c4 & 4) ? 1 : 0);
        As[basep + 0] = f2tf(v.x);
        As[basep + 2] = f2tf(v.y);
        As[basep + 4] = f2tf(v.z);
        As[basep + 6] = f2tf(v.w);
    }
}

__device__ __forceinline__ void load_W_tile(const float* __restrict__ W, unsigned* Wp,
                                            int ldw, int NC, int c0, int tid) {
#pragma unroll
    for (int i = 0; i < 8; i++) {
        int f = tid + i * 256;
        int row = f >> 5;           // k index 0..63
        int c4 = (f & 31) * 4;      // col 0..124
        float4 v = make_float4(0.f, 0.f, 0.f, 0.f);
        if (c0 + c4 < NC) v = *(const float4*)(W + (size_t)row * ldw + c0 + c4);
        int kb = row >> 3;
        int tr = row & 7;
        int half = (tr >= 4) ? 1 : 0;
        int tg = tr & 3;
        unsigned* base = Wp + (kb * 4 + tg) * WP_LD + half;
        base[(c4 + 0) * 2] = f2tf(v.x);
        base[(c4 + 1) * 2] = f2tf(v.y);
        base[(c4 + 2) * 2] = f2tf(v.z);
        base[(c4 + 3) * 2] = f2tf(v.w);
    }
}

__device__ __forceinline__ void gemm_mainloop(const unsigned* As, const unsigned* Wp,
                                              float acc[2][8][4], int wm, int wn,
                                              int g, int tg) {
#pragma unroll
    for (int kb = 0; kb < 8; kb++) {
        unsigned a[2][4];
#pragma unroll
        for (int mt = 0; mt < 2; mt++) {
            int rb = wm * 32 + mt * 16;
            uint2 pa = *(const uint2*)&As[(rb + g) * AS_LD + kb * 8 + tg * 2];
            uint2 pb = *(const uint2*)&As[(rb + 8 + g) * AS_LD + kb * 8 + tg * 2];
            a[mt][0] = pa.x; a[mt][2] = pa.y;
            a[mt][1] = pb.x; a[mt][3] = pb.y;
        }
        const unsigned* wrow = Wp + (kb * 4 + tg) * WP_LD;
#pragma unroll
        for (int nt = 0; nt < 8; nt++) {
            int cb = wn * 64 + nt * 8 + g;
            uint2 b01 = *(const uint2*)&wrow[cb * 2];
            mma_tf32(acc[0][nt], a[0][0], a[0][1], a[0][2], a[0][3], b01.x, b01.y);
            mma_tf32(acc[1][nt], a[1][0], a[1][1], a[1][2], a[1][3], b01.x, b01.y);
        }
    }
}

__global__ void gemm_tf32(const float* __restrict__ A, const float* __restrict__ W,
                          int ldw, int NC, float* __restrict__ C, __half* __restrict__ Ch,
                          int ldc, int M, const float* __restrict__ bias,
                          const int* __restrict__ gid, float* __restrict__ pool) {
    extern __shared__ unsigned smem_u[];
    unsigned* As = smem_u;
    unsigned* Wp = smem_u + 128 * AS_LD;
    int tid = threadIdx.x;
    int warp = tid >> 5, lane = tid & 31;
    int g = lane >> 2, tg = lane & 3;
    int wm = warp & 3, wn = warp >> 2;
    int r0 = blockIdx.y * 128;
    int c0 = blockIdx.x * 128;

    load_A_tile(A, As, r0, M, tid);
    load_W_tile(W, Wp, ldw, NC, c0, tid);
    __syncthreads();

    float acc[2][8][4];
#pragma unroll
    for (int mt = 0; mt < 2; mt++)
#pragma unroll
        for (int nt = 0; nt < 8; nt++)
#pragma unroll
            for (int q = 0; q < 4; q++) acc[mt][nt][q] = 0.f;

    gemm_mainloop(As, Wp, acc, wm, wn, g, tg);

#pragma unroll
    for (int mt = 0; mt < 2; mt++) {
#pragma unroll
        for (int nt = 0; nt < 8; nt++) {
            int col = c0 + wn * 64 + nt * 8 + tg * 2;
            if (col >= NC) continue;
            float bv0 = 0.f, bv1 = 0.f;
            if (bias) { bv0 = bias[col]; bv1 = bias[col + 1]; }
            int rowA = r0 + wm * 32 + mt * 16 + g;
#pragma unroll
            for (int half = 0; half < 2; half++) {
                int row = rowA + half * 8;
                if (row >= M) continue;
                float v0 = acc[mt][nt][half * 2 + 0] + bv0;
                float v1 = acc[mt][nt][half * 2 + 1] + bv1;
                if (Ch) {
                    *(__half2*)(Ch + (size_t)row * ldc + col) = __floats2half2_rn(v0, v1);
                } else {
                    *(float2*)(C + (size_t)row * ldc + col) = make_float2(v0, v1);
                    if (pool) {
                        int gi = gid[row];
                        atomicAdd(&pool[gi * HF + col], v0);
                        atomicAdd(&pool[gi * HF + col + 1], v1);
                    }
                }
            }
        }
    }
}

__global__ void gemm_fr1(const float* __restrict__ A, const float* __restrict__ Wf,
                         const float* __restrict__ Wr, __half* __restrict__ feat1,
                         __half* __restrict__ res1, int M) {
    extern __shared__ unsigned smem_u[];
    unsigned* As = smem_u;
    unsigned* Wp = smem_u + 128 * AS_LD;
    int tid = threadIdx.x;
    int warp = tid >> 5, lane = tid & 31;
    int g = lane >> 2, tg = lane & 3;
    int wm = warp & 3, wn = warp >> 2;
    int r0 = blockIdx.y * 128;
    int bx = blockIdx.x;
    int c0 = (bx & 3) * 128;
    const float* W = (bx >= 4) ? Wr : Wf;
    __half* Out = (bx >= 4) ? res1 : feat1;

    load_A_tile(A, As, r0, M, tid);
    load_W_tile(W, Wp, 512, 512, c0, tid);
    __syncthreads();

    float acc[2][8][4];
#pragma unroll
    for (int mt = 0; mt < 2; mt++)
#pragma unroll
        for (int nt = 0; nt < 8; nt++)
#pragma unroll
            for (int q = 0; q < 4; q++) acc[mt][nt][q] = 0.f;

    gemm_mainloop(As, Wp, acc, wm, wn, g, tg);

#pragma unroll
    for (int mt = 0; mt < 2; mt++) {
#pragma unroll
        for (int nt = 0; nt < 8; nt++) {
            int col = c0 + wn * 64 + nt * 8 + tg * 2;
            int rowA = r0 + wm * 32 + mt * 16 + g;
#pragma unroll
            for (int half = 0; half < 2; half++) {
                int row = rowA + half * 8;
                if (row >= M) continue;
                float v0 = acc[mt][nt][half * 2 + 0];
                float v1 = acc[mt][nt][half * 2 + 1];
                *(__half2*)(Out + (size_t)row * 512 + col) = __floats2half2_rn(v0, v1);
            }
        }
    }
}

// ---------------- el/er for layer 1 ----------------
__global__ void elr1_kernel(const __half* __restrict__ feat1, const float* __restrict__ al,
                            const float* __restrict__ ar, float* __restrict__ el,
                            float* __restrict__ er, int M) {
    __shared__ float sal[512], sar[512];
    int tid = threadIdx.x;
    for (int i = tid; i < 512; i += 256) { sal[i] = al[i]; sar[i] = ar[i]; }
    __syncthreads();
    int warp = tid >> 5, lane = tid & 31;
    int n = blockIdx.x * 8 + warp;
    if (n >= M) return;
    const __half* fp = feat1 + (size_t)n * 512 + lane * 16;
    uint4 u0 = *(const uint4*)fp;
    uint4 u1 = *(const uint4*)(fp + 8);
    const __half2* h0 = (const __half2*)&u0;
    const __half2* h1 = (const __half2*)&u1;
    float pl = 0.f, pr = 0.f;
#pragma unroll
    for (int j = 0; j < 4; j++) {
        float2 f = __half22float2(h0[j]);
        pl += f.x * sal[lane * 16 + 2 * j] + f.y * sal[lane * 16 + 2 * j + 1];
        pr += f.x * sar[lane * 16 + 2 * j] + f.y * sar[lane * 16 + 2 * j + 1];
    }
#pragma unroll
    for (int j = 0; j < 4; j++) {
        float2 f = __half22float2(h1[j]);
        pl += f.x * sal[lane * 16 + 8 + 2 * j] + f.y * sal[lane * 16 + 8 + 2 * j + 1];
        pr += f.x * sar[lane * 16 + 8 + 2 * j] + f.y * sar[lane * 16 + 8 + 2 * j + 1];
    }
    pl += __shfl_xor_sync(0xffffffffu, pl, 1);
    pl += __shfl_xor_sync(0xffffffffu, pl, 2);
    pr += __shfl_xor_sync(0xffffffffu, pr, 1);
    pr += __shfl_xor_sync(0xffffffffu, pr, 2);
    if ((lane & 3) == 0) {
        int h = lane >> 2;
        el[n * HEADS + h] = pl;
        er[n * HEADS + h] = pr;
    }
}

// ---------------- layer-1 aggregation: 4 warps per node (2 heads/warp) -------------
__global__ void agg1_kernel(const __half* __restrict__ feat1, const __half* __restrict__ res1,
                            const float* __restrict__ el, const float* __restrict__ er,
                            const int* __restrict__ off, const int* __restrict__ degv,
                            const int* __restrict__ srcs, const float* __restrict__ b1,
                            const int* __restrict__ gid, float* __restrict__ h1,
                            float* __restrict__ pool, int M) {
    __shared__ float sy[2][512];
    int warp = threadIdx.x >> 5, lane = threadIdx.x & 31;
    int nid = warp >> 2;
    int wn = warp & 3;
    int n = blockIdx.x * 2 + nid;
    bool active = (n < M);
    int hh = wn * 2 + (lane >> 4);
    int p = lane & 15;
    int col = hh * 64 + p * 4;

    int start = 0, deg = 0;
    float erh = 0.f;
    if (active) {
        start = off[n];
        deg = degv[n];
        erh = er[n * HEADS + hh];
    }

    float m = -1e30f, den = 0.f;
    float acc[4] = {0.f, 0.f, 0.f, 0.f};

    for (int k0 = 0; k0 < deg; k0 += 4) {
        int cnt = deg - k0;
        int s4[4];
        s4[0] = srcs[start + k0];
#pragma unroll
        for (int i = 1; i < 4; i++)
            s4[i] = (i < cnt) ? srcs[start + k0 + i] : s4[0];
        float e4[4];
#pragma unroll
        for (int i = 0; i < 4; i++) e4[i] = el[s4[i] * HEADS + hh];
        uint2 f4[4];
#pragma unroll
        for (int i = 0; i < 4; i++)
            f4[i] = *(const uint2*)(feat1 + (size_t)s4[i] * 512 + col);
        float bm = -1e30f;
#pragma unroll
        for (int i = 0; i < 4; i++) {
            float e = e4[i] + erh;
            e = e > 0.f ? e : 0.2f * e;
            e4[i] = (i < cnt) ? e : -1e30f;
            bm = fmaxf(bm, e4[i]);
        }
        if (bm > m) {
            float c = __expf(m - bm);
            den *= c;
#pragma unroll
            for (int q = 0; q < 4; q++) acc[q] *= c;
            m = bm;
        }
#pragma unroll
        for (int i = 0; i < 4; i++) {
            float pw = __expf(e4[i] - m);
            den += pw;
            __half2 lo = *(__half2*)&f4[i].x;
            __half2 hi = *(__half2*)&f4[i].y;
            float2 v0 = __half22float2(lo);
            float2 v1 = __half22float2(hi);
            acc[0] += pw * v0.x;
            acc[1] += pw * v0.y;
            acc[2] += pw * v1.x;
            acc[3] += pw * v1.y;
        }
    }
    float inv = (deg > 0) ? (1.f / den) : 0.f;

    float x[4] = {0.f, 0.f, 0.f, 0.f};
    float s1 = 0.f, s2 = 0.f;
    if (active) {
        uint2 rv = *(const uint2*)(res1 + (size_t)n * 512 + col);
        __half2 rlo = *(__half2*)&rv.x;
        __half2 rhi = *(__half2*)&rv.y;
        float2 r0 = __half22float2(rlo);
        float2 r1 = __half22float2(rhi);
        float rr[4] = {r0.x, r0.y, r1.x, r1.y};
        float4 bv = *(const float4*)(b1 + col);
        float bb[4] = {bv.x, bv.y, bv.z, bv.w};
#pragma unroll
        for (int q = 0; q < 4; q++) {
            float val = acc[q] * inv + rr[q] + bb[q];
            val = elu_fast(val);
            x[q] = val;
            s1 += val;
            s2 += val * val;
        }
    }
#pragma unroll
    for (int o = 1; o <= 8; o <<= 1) {
        s1 += __shfl_xor_sync(0xffffffffu, s1, o);
        s2 += __shfl_xor_sync(0xffffffffu, s2, o);
    }
    float mu = s1 * (1.f / 64.f);
    float var = s2 * (1.f / 64.f) - mu * mu;
    float rs = rsqrtf(var + 1e-5f);
    if (active) {
#pragma unroll
        for (int q = 0; q < 4; q++)
            sy[nid][col + q] = (x[q] - mu) * rs;
    }
    __syncthreads();
    if (wn == 0 && active) {
        int d0 = lane * 2;
        float y0 = 0.f, y1 = 0.f;
#pragma unroll
        for (int hq = 0; hq < 8; hq++) {
            y0 += sy[nid][hq * 64 + d0];
            y1 += sy[nid][hq * 64 + d0 + 1];
        }
        y0 *= 0.125f;
        y1 *= 0.125f;
        int g = gid[n];
        *(float2*)(h1 + (size_t)n * HF + d0) = make_float2(y0, y1);
        atomicAdd(&pool[g * HF + d0 + 0], y0);
        atomicAdd(&pool[g * HF + d0 + 1], y1);
    }
}

// ---------------- el/er for layer 2 (fp16 feat2) ----------------
__global__ void elr2_kernel(const __half* __restrict__ feat2, const float* __restrict__ al,
                            const float* __restrict__ ar, float* __restrict__ el,
                            float* __restrict__ er, int M) {
    int warp = threadIdx.x >> 5, lane = threadIdx.x & 31;
    int n = blockIdx.x * 8 + warp;
    if (n >= M) return;
    int d0 = lane * 2;
    float2 f = __half22float2(*(const __half2*)(feat2 + (size_t)n * HF + d0));
    float pl = f.x * al[d0] + f.y * al[d0 + 1];
    float pr = f.x * ar[d0] + f.y * ar[d0 + 1];
#pragma unroll
    for (int o = 16; o > 0; o >>= 1) {
        pl += __shfl_xor_sync(0xffffffffu, pl, o);
        pr += __shfl_xor_sync(0xffffffffu, pr, o);
    }
    if (lane == 0) { el[n] = pl; er[n] = pr; }
}

// ---------------- layer-2 aggregation: one warp per node, batch-8 (R12 version) ---
__global__ void agg2_kernel(const __half* __restrict__ feat2, const float* __restrict__ el,
                            const float* __restrict__ er, const int* __restrict__ off,
                            const int* __restrict__ degv, const int* __restrict__ srcs,
                            const float* __restrict__ h1, const float* __restrict__ b2,
                            const int* __restrict__ gid, float* __restrict__ pool, int M) {
    int warp = threadIdx.x >> 5, lane = threadIdx.x & 31;
    int n = blockIdx.x * 8 + warp;
    if (n >= M) return;
    int d0 = lane * 2;
    int start = off[n];
    int deg = degv[n];
    float ern = er[n];

    float m = -1e30f, den = 0.f, a0 = 0.f, a1 = 0.f;

    for (int k0 = 0; k0 < deg; k0 += 8) {
        int cnt = deg - k0;
        int s8[8];
        s8[0] = srcs[start + k0];
#pragma unroll
        for (int i = 1; i < 8; i++)
            s8[i] = (i < cnt) ? srcs[start + k0 + i] : s8[0];
        float e8[8];
#pragma unroll
        for (int i = 0; i < 8; i++) e8[i] = el[s8[i]];
        unsigned f8[8];
#pragma unroll
        for (int i = 0; i < 8; i++)
            f8[i] = *(const unsigned*)(feat2 + (size_t)s8[i] * HF + d0);
        float bm = -1e30f;
#pragma unroll
        for (int i = 0; i < 8; i++) {
            float e = e8[i] + ern;
            e = e > 0.f ? e : 0.2f * e;
            e8[i] = (i < cnt) ? e : -1e30f;
            bm = fmaxf(bm, e8[i]);
        }
        if (bm > m) {
            float c = __expf(m - bm);
            den *= c; a0 *= c; a1 *= c;
            m = bm;
        }
#pragma unroll
        for (int i = 0; i < 8; i++) {
            float p = __expf(e8[i] - m);
            den += p;
            float2 v = __half22float2(*(const __half2*)&f8[i]);
            a0 += p * v.x;
            a1 += p * v.y;
        }
    }
    float inv = (deg > 0) ? (1.f / den) : 0.f;
    float2 hv = *(const float2*)(h1 + (size_t)n * HF + d0);
    float x0 = elu_fast(a0 * inv + hv.x + b2[d0]);
    float x1 = elu_fast(a1 * inv + hv.y + b2[d0 + 1]);
    float s1 = x0 + x1;
    float s2 = x0 * x0 + x1 * x1;
#pragma unroll
    for (int o = 16; o > 0; o >>= 1) {
        s1 += __shfl_xor_sync(0xffffffffu, s1, o);
        s2 += __shfl_xor_sync(0xffffffffu, s2, o);
    }
    float mu = s1 * (1.f / 64.f);
    float var = s2 * (1.f / 64.f) - mu * mu;
    float rs = rsqrtf(var + 1e-5f);
    float y0 = (x0 - mu) * rs;
    float y1 = (x1 - mu) * rs;
    int g = gid[n];
    atomicAdd(&pool[g * HF + d0 + 0], y0);
    atomicAdd(&pool[g * HF + d0 + 1], y1);
}

// ---------------- fused graph head ----------------
__global__ void head_kernel(const float* __restrict__ p0, const float* __restrict__ p1,
                            const float* __restrict__ p2, const float* __restrict__ gW1,
                            const float* __restrict__ gb1, const float* __restrict__ gW2,
                            const float* __restrict__ gb2, const float* __restrict__ mW0,
                            const float* __restrict__ mb0, const float* __restrict__ mW1,
                            const float* __restrict__ mb1, const float* __restrict__ mW2,
                            const float* __restrict__ mb2, float* __restrict__ out) {
    __shared__ float a1[64], a2[64], hg[64], t0s[256], t1s[256];
    int g = blockIdx.x, t = threadIdx.x;
    if (t < 64) { a1[t] = p1[g * 64 + t]; a2[t] = p2[g * 64 + t]; }
    __syncthreads();
    if (t < 64) {
        float s1 = gb1[t], s2 = gb2[t];
        for (int k = 0; k < 64; k++) {
            s1 += a1[k] * gW1[k * 64 + t];
            s2 += a2[k] * gW2[k * 64 + t];
        }
        s1 = s1 > 0.f ? s1 : 0.01f * s1;
        s2 = s2 > 0.f ? s2 : 0.01f * s2;
        hg[t] = p0[g * 64 + t] + s1 + s2;
    }
    __syncthreads();
    float acc = mb0[t];
    for (int k = 0; k < 64; k++) acc += hg[k] * mW0[k * 256 + t];
    t0s[t] = fmaxf(acc, 0.f);
    __syncthreads();
    acc = mb1[t];
    for (int k = 0; k < 256; k++) acc += t0s[k] * mW1[k * 256 + t];
    t1s[t] = fmaxf(acc, 0.f);
    __syncthreads();
    acc = mb2[t];
    for (int k = 0; k < 256; k++) acc += t1s[k] * mW2[k * 256 + t];
    out[g * 256 + t] = acc;
}

// ---------------- launch ----------------
extern "C" void kernel_launch(void* const* d_in, const int* in_sizes, int n_in,
                              void* d_out, int out_size) {
    const float* X     = (const float*)d_in[0];
    const int*   src   = (const int*)d_in[1];
    const int*   dst   = (const int*)d_in[2];
    const int*   gid   = (const int*)d_in[3];
    const float* projW = (const float*)d_in[4];
    const float* projb = (const float*)d_in[5];
    const float* fcW1  = (const float*)d_in[6];
    const float* al1   = (const float*)d_in[7];
    const float* ar1   = (const float*)d_in[8];
    const float* resW1 = (const float*)d_in[9];
    const float* b1    = (const float*)d_in[10];
    const float* fcW2  = (const float*)d_in[11];
    const float* al2   = (const float*)d_in[12];
    const float* ar2   = (const float*)d_in[13];
    const float* b2    = (const float*)d_in[14];
    const float* gW1   = (const float*)d_in[15];
    const float* gb1   = (const float*)d_in[16];
    const float* gW2   = (const float*)d_in[17];
    const float* gb2   = (const float*)d_in[18];
    const float* mW0   = (const float*)d_in[19];
    const float* mb0   = (const float*)d_in[20];
    const float* mW1   = (const float*)d_in[21];
    const float* mb1   = (const float*)d_in[22];
    const float* mW2   = (const float*)d_in[23];
    const float* mb2   = (const float*)d_in[24];

    int M = in_sizes[0] / HF;
    int E = in_sizes[1];

    float *h, *el1, *er1, *h1, *el2, *er2;
    float *p0, *p1, *p2;
    __half *feat1, *res1, *feat2;
    int *deg, *off, *cur, *bsum, *srcs;
    cudaGetSymbolAddress((void**)&h, g_h);
    cudaGetSymbolAddress((void**)&feat1, g_feat1);
    cudaGetSymbolAddress((void**)&res1, g_res1);
    cudaGetSymbolAddress((void**)&el1, g_el1);
    cudaGetSymbolAddress((void**)&er1, g_er1);
    cudaGetSymbolAddress((void**)&h1, g_h1);
    cudaGetSymbolAddress((void**)&feat2, g_feat2);
    cudaGetSymbolAddress((void**)&el2, g_el2);
    cudaGetSymbolAddress((void**)&er2, g_er2);
    cudaGetSymbolAddress((void**)&deg, g_deg);
    cudaGetSymbolAddress((void**)&off, g_off);
    cudaGetSymbolAddress((void**)&cur, g_cur);
    cudaGetSymbolAddress((void**)&bsum, g_bsum);
    cudaGetSymbolAddress((void**)&srcs, g_srcs);
    cudaGetSymbolAddress((void**)&p0, g_p0);
    cudaGetSymbolAddress((void**)&p1, g_p1);
    cudaGetSymbolAddress((void**)&p2, g_p2);

    static int smem_set = 0;
    if (!smem_set) {
        cudaFuncSetAttribute(gemm_tf32, cudaFuncAttributeMaxDynamicSharedMemorySize,
                             GEMM_SMEM);
        cudaFuncSetAttribute(gemm_fr1, cudaFuncAttributeMaxDynamicSharedMemorySize,
                             GEMM_SMEM);
        smem_set = 1;
    }

    int nwb = (M + 7) / 8;
    int nwb2 = (M + 1) / 2;
    int rowTiles = (M + 127) / 128;
    int scanBlocks = (M + 255) / 256;

    init_kernel<<<(M + 255) / 256, 256>>>(deg, p0, p1, p2, M);                        // 1
    hist_kernel<<<(E + 255) / 256, 256>>>(dst, deg, E);                               // 2
    gemm_tf32<<<dim3(1, rowTiles), 256, GEMM_SMEM>>>(X, projW, HF, HF, h, nullptr,
                                                     HF, M, projb, gid, p0);          // 3
    gemm_fr1<<<dim3(8, rowTiles), 256, GEMM_SMEM>>>(h, fcW1, resW1, feat1, res1, M);  // 4 <- capture
    scan1_kernel<<<scanBlocks, 256>>>(deg, off, bsum, M);                             // 5
    scan2_kernel<<<scanBlocks, 256>>>(bsum, off, cur, M, scanBlocks);                 // 6
    scatter_kernel<<<(E + 255) / 256, 256>>>(src, dst, cur, srcs, E);                 // 7
    elr1_kernel<<<nwb, 256>>>(feat1, al1, ar1, el1, er1, M);                          // 8
    agg1_kernel<<<nwb2, 256>>>(feat1, res1, el1, er1, off, deg, srcs, b1, gid,
                               h1, p1, M);                                            // 9
    gemm_tf32<<<dim3(1, rowTiles), 256, GEMM_SMEM>>>(h1, fcW2, HF, HF, nullptr,
                                                     feat2, HF, M, nullptr, nullptr,
                                                     nullptr);                        // 10
    elr2_kernel<<<nwb, 256>>>(feat2, al2, ar2, el2, er2, M);                          // 11
    agg2_kernel<<<nwb, 256>>>(feat2, el2, er2, off, deg, srcs, h1, b2, gid, p2, M);   // 12
    head_kernel<<<GG, MLPD>>>(p0, p1, p2, gW1, gb1, gW2, gb2, mW0, mb0, mW1, mb1,
                              mW2, mb2, (float*)d_out);                               // 13
}

// round 15
// speedup vs baseline: 1.1095x; 1.0829x over previous
#include <cuda_runtime.h>
#include <cuda_fp16.h>
#include <math.h>

#define NN 30000
#define EE 480000
#define GG 64
#define HF 64
#define HEADS 8
#define MLPD 256

// ---------------- device scratch ----------------
__device__ float  g_h[NN * HF];
__device__ __half g_feat1[(size_t)NN * 512];
__device__ __half g_res1[(size_t)NN * 512];
__device__ float  g_el1[NN * HEADS];
__device__ float  g_er1[NN * HEADS];
__device__ float  g_h1[NN * HF];
__device__ __half g_feat2[NN * HF];
__device__ float  g_el2[NN];
__device__ float  g_er2[NN];
__device__ int    g_deg[NN];
__device__ int    g_off[NN];
__device__ int    g_cur[NN];
__device__ int    g_bsum[256];
__device__ int    g_srcs[EE];
__device__ float  g_p0[GG * HF];
__device__ float  g_p1[GG * HF];
__device__ float  g_p2[GG * HF];

// ---------------- helpers ----------------
__device__ __forceinline__ unsigned f2tf(float f) {
    unsigned r;
    asm("cvt.rna.tf32.f32 %0, %1;" : "=r"(r) : "f"(f));
    return r;
}

__device__ __forceinline__ void mma_tf32(float* c, unsigned a0, unsigned a1,
                                         unsigned a2, unsigned a3,
                                         unsigned b0, unsigned b1) {
    asm("mma.sync.aligned.m16n8k8.row.col.f32.tf32.tf32.f32 "
        "{%0,%1,%2,%3},{%4,%5,%6,%7},{%8,%9},{%0,%1,%2,%3};"
        : "+f"(c[0]), "+f"(c[1]), "+f"(c[2]), "+f"(c[3])
        : "r"(a0), "r"(a1), "r"(a2), "r"(a3), "r"(b0), "r"(b1));
}

__device__ __forceinline__ float elu_fast(float x) {
    return x > 0.f ? x : (__expf(x) - 1.f);
}

// ---------------- init ----------------
__global__ void init_kernel(int* deg, float* p0, float* p1, float* p2, int n) {
    int i = blockIdx.x * blockDim.x + threadIdx.x;
    if (i < n) deg[i] = 0;
    if (i < GG * HF) { p0[i] = 0.f; p1[i] = 0.f; p2[i] = 0.f; }
}

// ---------------- CSR build ----------------
__global__ void hist_kernel(const int* __restrict__ dst, int* __restrict__ deg, int E) {
    int e = blockIdx.x * blockDim.x + threadIdx.x;
    if (e < E) atomicAdd(&deg[dst[e]], 1);
}

__global__ void scan1_kernel(const int* __restrict__ deg, int* __restrict__ off,
                             int* __restrict__ bsum, int n) {
    __shared__ int sm[256];
    int t = threadIdx.x;
    int i = blockIdx.x * 256 + t;
    int v = (i < n) ? deg[i] : 0;
    sm[t] = v;
    __syncthreads();
#pragma unroll
    for (int o = 1; o < 256; o <<= 1) {
        int x = (t >= o) ? sm[t - o] : 0;
        __syncthreads();
        sm[t] += x;
        __syncthreads();
    }
    if (i < n) off[i] = sm[t] - v;
    if (t == 255) bsum[blockIdx.x] = sm[255];
}

__global__ void scan2_kernel(const int* __restrict__ bsum, int* __restrict__ off,
                             int* __restrict__ cur, int n, int nblocks) {
    __shared__ int sb[256];
    int t = threadIdx.x;
    sb[t] = (t < nblocks) ? bsum[t] : 0;
    __syncthreads();
#pragma unroll
    for (int o = 1; o < 256; o <<= 1) {
        int x = (t >= o) ? sb[t - o] : 0;
        __syncthreads();
        sb[t] += x;
        __syncthreads();
    }
    int b = blockIdx.x;
    int base = (b > 0) ? sb[b - 1] : 0;
    int i = b * 256 + t;
    if (i < n) {
        int o = off[i] + base;
        off[i] = o;
        cur[i] = o;
    }
}

__global__ void scatter_kernel(const int* __restrict__ src, const int* __restrict__ dst,
                               int* __restrict__ cur, int* __restrict__ srcs, int E) {
    int e = blockIdx.x * blockDim.x + threadIdx.x;
    if (e < E) {
        int d = dst[e];
        int pos = atomicAdd(&cur[d], 1);
        srcs[pos] = src[e];
    }
}

// ---------------- tf32 tensor-core GEMMs (R12 layout: WS_LD=136 scalar B) ---------
#define AS_LD 72
#define WS_LD 136
#define GEMM_SMEM ((128 * AS_LD + 64 * WS_LD) * 4)
#define GEMM_SMEM_FR (GEMM_SMEM + 256 * 4)   // + al/ar slice (128 each)

__device__ __forceinline__ void load_A_tile(const float* __restrict__ A, unsigned* As,
                                            int r0, int M, int tid) {
#pragma unroll
    for (int i = 0; i < 8; i++) {
        int f = tid + i * 256;
        int row = f >> 4;
        int c4 = (f & 15) * 4;
        float4 v = make_float4(0.f, 0.f, 0.f, 0.f);
        if (r0 + row < M) v = *(const float4*)(A + (size_t)(r0 + row) * 64 + c4);
        int kb = c4 >> 3;
        int basep = row * AS_LD + kb * 8 + ((c4 & 4) ? 1 : 0);
        As[basep + 0] = f2tf(v.x);
        As[basep + 2] = f2tf(v.y);
        As[basep + 4] = f2tf(v.z);
        As[basep + 6] = f2tf(v.w);
    }
}

__device__ __forceinline__ void load_W_tile(const float* __restrict__ W, unsigned* Ws,
                                            int ldw, int NC, int c0, int tid) {
#pragma unroll
    for (int i = 0; i < 8; i++) {
        int f = tid + i * 256;
        int row = f >> 5;
        int c4 = (f & 31) * 4;
        float4 v = make_float4(0.f, 0.f, 0.f, 0.f);
        if (c0 + c4 < NC) v = *(const float4*)(W + (size_t)row * ldw + c0 + c4);
        Ws[row * WS_LD + c4 + 0] = f2tf(v.x);
        Ws[row * WS_LD + c4 + 1] = f2tf(v.y);
        Ws[row * WS_LD + c4 + 2] = f2tf(v.z);
        Ws[row * WS_LD + c4 + 3] = f2tf(v.w);
    }
}

__device__ __forceinline__ void gemm_mainloop(const unsigned* As, const unsigned* Ws,
                                              float acc[2][8][4], int wm, int wn,
                                              int g, int tg) {
#pragma unroll
    for (int kb = 0; kb < 8; kb++) {
        unsigned a[2][4];
#pragma unroll
        for (int mt = 0; mt < 2; mt++) {
            int rb = wm * 32 + mt * 16;
            uint2 pa = *(const uint2*)&As[(rb + g) * AS_LD + kb * 8 + tg * 2];
            uint2 pb = *(const uint2*)&As[(rb + 8 + g) * AS_LD + kb * 8 + tg * 2];
            a[mt][0] = pa.x; a[mt][2] = pa.y;
            a[mt][1] = pb.x; a[mt][3] = pb.y;
        }
        int kk = kb * 8;
#pragma unroll
        for (int nt = 0; nt < 8; nt++) {
            int cb = wn * 64 + nt * 8 + g;
            unsigned b0 = Ws[(kk + tg) * WS_LD + cb];
            unsigned b1 = Ws[(kk + tg + 4) * WS_LD + cb];
            mma_tf32(acc[0][nt], a[0][0], a[0][1], a[0][2], a[0][3], b0, b1);
            mma_tf32(acc[1][nt], a[1][0], a[1][1], a[1][2], a[1][3], b0, b1);
        }
    }
}

__global__ void gemm_tf32(const float* __restrict__ A, const float* __restrict__ W,
                          int ldw, int NC, float* __restrict__ C, __half* __restrict__ Ch,
                          int ldc, int M, const float* __restrict__ bias,
                          const int* __restrict__ gid, float* __restrict__ pool) {
    extern __shared__ unsigned smem_u[];
    unsigned* As = smem_u;
    unsigned* Ws = smem_u + 128 * AS_LD;
    int tid = threadIdx.x;
    int warp = tid >> 5, lane = tid & 31;
    int g = lane >> 2, tg = lane & 3;
    int wm = warp & 3, wn = warp >> 2;
    int r0 = blockIdx.y * 128;
    int c0 = blockIdx.x * 128;

    load_A_tile(A, As, r0, M, tid);
    load_W_tile(W, Ws, ldw, NC, c0, tid);
    __syncthreads();

    float acc[2][8][4];
#pragma unroll
    for (int mt = 0; mt < 2; mt++)
#pragma unroll
        for (int nt = 0; nt < 8; nt++)
#pragma unroll
            for (int q = 0; q < 4; q++) acc[mt][nt][q] = 0.f;

    gemm_mainloop(As, Ws, acc, wm, wn, g, tg);

#pragma unroll
    for (int mt = 0; mt < 2; mt++) {
#pragma unroll
        for (int nt = 0; nt < 8; nt++) {
            int col = c0 + wn * 64 + nt * 8 + tg * 2;
            if (col >= NC) continue;
            float bv0 = 0.f, bv1 = 0.f;
            if (bias) { bv0 = bias[col]; bv1 = bias[col + 1]; }
            int rowA = r0 + wm * 32 + mt * 16 + g;
#pragma unroll
            for (int half = 0; half < 2; half++) {
                int row = rowA + half * 8;
                if (row >= M) continue;
                float v0 = acc[mt][nt][half * 2 + 0] + bv0;
                float v1 = acc[mt][nt][half * 2 + 1] + bv1;
                if (Ch) {
                    *(__half2*)(Ch + (size_t)row * ldc + col) = __floats2half2_rn(v0, v1);
                } else {
                    *(float2*)(C + (size_t)row * ldc + col) = make_float2(v0, v1);
                    if (pool) {
                        int gi = gid[row];
                        atomicAdd(&pool[gi * HF + col], v0);
                        atomicAdd(&pool[gi * HF + col + 1], v1);
                    }
                }
            }
        }
    }
}

// fused fc1+res1 with el1/er1 computed in the epilogue of feat blocks.
__global__ void gemm_fr1(const float* __restrict__ A, const float* __restrict__ Wf,
                         const float* __restrict__ Wr, __half* __restrict__ feat1,
                         __half* __restrict__ res1, const float* __restrict__ al1,
                         const float* __restrict__ ar1, float* __restrict__ el,
                         float* __restrict__ er, int M) {
    extern __shared__ unsigned smem_u[];
    unsigned* As = smem_u;
    unsigned* Ws = smem_u + 128 * AS_LD;
    float* al_s = (float*)(smem_u + 128 * AS_LD + 64 * WS_LD);
    float* ar_s = al_s + 128;
    int tid = threadIdx.x;
    int warp = tid >> 5, lane = tid & 31;
    int g = lane >> 2, tg = lane & 3;
    int wm = warp & 3, wn = warp >> 2;
    int r0 = blockIdx.y * 128;
    int bx = blockIdx.x;
    int c0 = (bx & 3) * 128;
    bool isFeat = (bx < 4);
    const float* W = isFeat ? Wf : Wr;
    __half* Out = isFeat ? feat1 : res1;

    load_A_tile(A, As, r0, M, tid);
    load_W_tile(W, Ws, 512, 512, c0, tid);
    if (isFeat && tid < 128) {
        al_s[tid] = al1[c0 + tid];
        ar_s[tid] = ar1[c0 + tid];
    }
    __syncthreads();

    float acc[2][8][4];
#pragma unroll
    for (int mt = 0; mt < 2; mt++)
#pragma unroll
        for (int nt = 0; nt < 8; nt++)
#pragma unroll
            for (int q = 0; q < 4; q++) acc[mt][nt][q] = 0.f;

    gemm_mainloop(As, Ws, acc, wm, wn, g, tg);

    float pl[2][2] = {{0.f, 0.f}, {0.f, 0.f}};
    float pr[2][2] = {{0.f, 0.f}, {0.f, 0.f}};

#pragma unroll
    for (int mt = 0; mt < 2; mt++) {
#pragma unroll
        for (int nt = 0; nt < 8; nt++) {
            int lcol = wn * 64 + nt * 8 + tg * 2;
            int col = c0 + lcol;
            int rowA = r0 + wm * 32 + mt * 16 + g;
            float a0 = 0.f, a1 = 0.f, b0 = 0.f, b1 = 0.f;
            if (isFeat) {
                a0 = al_s[lcol]; a1 = al_s[lcol + 1];
                b0 = ar_s[lcol]; b1 = ar_s[lcol + 1];
            }
#pragma unroll
            for (int half = 0; half < 2; half++) {
                int row = rowA + half * 8;
                if (row >= M) continue;
                float v0 = acc[mt][nt][half * 2 + 0];
                float v1 = acc[mt][nt][half * 2 + 1];
                *(__half2*)(Out + (size_t)row * 512 + col) = __floats2half2_rn(v0, v1);
                if (isFeat) {
                    pl[mt][half] += v0 * a0 + v1 * a1;
                    pr[mt][half] += v0 * b0 + v1 * b1;
                }
            }
        }
    }

    if (isFeat) {
        int head = 2 * (bx & 3) + wn;
#pragma unroll
        for (int mt = 0; mt < 2; mt++) {
#pragma unroll
            for (int half = 0; half < 2; half++) {
                float l = pl[mt][half];
                float r = pr[mt][half];
                l += __shfl_xor_sync(0xffffffffu, l, 1);
                l += __shfl_xor_sync(0xffffffffu, l, 2);
                r += __shfl_xor_sync(0xffffffffu, r, 1);
                r += __shfl_xor_sync(0xffffffffu, r, 2);
                int row = r0 + wm * 32 + mt * 16 + g + half * 8;
                if (tg == 0 && row < M) {
                    el[row * HEADS + head] = l;
                    er[row * HEADS + head] = r;
                }
            }
        }
    }
}

// ---------------- layer-1 aggregation: 4 warps per node (2 heads/warp) -------------
__global__ void agg1_kernel(const __half* __restrict__ feat1, const __half* __restrict__ res1,
                            const float* __restrict__ el, const float* __restrict__ er,
                            const int* __restrict__ off, const int* __restrict__ degv,
                            const int* __restrict__ srcs, const float* __restrict__ b1,
                            const int* __restrict__ gid, float* __restrict__ h1,
                            float* __restrict__ pool, int M) {
    __shared__ float sy[2][512];
    int warp = threadIdx.x >> 5, lane = threadIdx.x & 31;
    int nid = warp >> 2;
    int wn = warp & 3;
    int n = blockIdx.x * 2 + nid;
    bool active = (n < M);
    int hh = wn * 2 + (lane >> 4);
    int p = lane & 15;
    int col = hh * 64 + p * 4;

    int start = 0, deg = 0;
    float erh = 0.f;
    if (active) {
        start = off[n];
        deg = degv[n];
        erh = er[n * HEADS + hh];
    }

    float m = -1e30f, den = 0.f;
    float acc[4] = {0.f, 0.f, 0.f, 0.f};

    for (int k0 = 0; k0 < deg; k0 += 4) {
        int cnt = deg - k0;
        int s4[4];
        s4[0] = srcs[start + k0];
#pragma unroll
        for (int i = 1; i < 4; i++)
            s4[i] = (i < cnt) ? srcs[start + k0 + i] : s4[0];
        float e4[4];
#pragma unroll
        for (int i = 0; i < 4; i++) e4[i] = el[s4[i] * HEADS + hh];
        uint2 f4[4];
#pragma unroll
        for (int i = 0; i < 4; i++)
            f4[i] = *(const uint2*)(feat1 + (size_t)s4[i] * 512 + col);
        float bm = -1e30f;
#pragma unroll
        for (int i = 0; i < 4; i++) {
            float e = e4[i] + erh;
            e = e > 0.f ? e : 0.2f * e;
            e4[i] = (i < cnt) ? e : -1e30f;
            bm = fmaxf(bm, e4[i]);
        }
        if (bm > m) {
            float c = __expf(m - bm);
            den *= c;
#pragma unroll
            for (int q = 0; q < 4; q++) acc[q] *= c;
            m = bm;
        }
#pragma unroll
        for (int i = 0; i < 4; i++) {
            float pw = __expf(e4[i] - m);
            den += pw;
            __half2 lo = *(__half2*)&f4[i].x;
            __half2 hi = *(__half2*)&f4[i].y;
            float2 v0 = __half22float2(lo);
            float2 v1 = __half22float2(hi);
            acc[0] += pw * v0.x;
            acc[1] += pw * v0.y;
            acc[2] += pw * v1.x;
            acc[3] += pw * v1.y;
        }
    }
    float inv = (deg > 0) ? (1.f / den) : 0.f;

    float x[4] = {0.f, 0.f, 0.f, 0.f};
    float s1 = 0.f, s2 = 0.f;
    if (active) {
        uint2 rv = *(const uint2*)(res1 + (size_t)n * 512 + col);
        __half2 rlo = *(__half2*)&rv.x;
        __half2 rhi = *(__half2*)&rv.y;
        float2 r0 = __half22float2(rlo);
        float2 r1 = __half22float2(rhi);
        float rr[4] = {r0.x, r0.y, r1.x, r1.y};
        float4 bv = *(const float4*)(b1 + col);
        float bb[4] = {bv.x, bv.y, bv.z, bv.w};
#pragma unroll
        for (int q = 0; q < 4; q++) {
            float val = acc[q] * inv + rr[q] + bb[q];
            val = elu_fast(val);
            x[q] = val;
            s1 += val;
            s2 += val * val;
        }
    }
#pragma unroll
    for (int o = 1; o <= 8; o <<= 1) {
        s1 += __shfl_xor_sync(0xffffffffu, s1, o);
        s2 += __shfl_xor_sync(0xffffffffu, s2, o);
    }
    float mu = s1 * (1.f / 64.f);
    float var = s2 * (1.f / 64.f) - mu * mu;
    float rs = rsqrtf(var + 1e-5f);
    if (active) {
#pragma unroll
        for (int q = 0; q < 4; q++)
            sy[nid][col + q] = (x[q] - mu) * rs;
    }
    __syncthreads();
    if (wn == 0 && active) {
        int d0 = lane * 2;
        float y0 = 0.f, y1 = 0.f;
#pragma unroll
        for (int hq = 0; hq < 8; hq++) {
            y0 += sy[nid][hq * 64 + d0];
            y1 += sy[nid][hq * 64 + d0 + 1];
        }
        y0 *= 0.125f;
        y1 *= 0.125f;
        int g = gid[n];
        *(float2*)(h1 + (size_t)n * HF + d0) = make_float2(y0, y1);
        atomicAdd(&pool[g * HF + d0 + 0], y0);
        atomicAdd(&pool[g * HF + d0 + 1], y1);
    }
}

// ---------------- el/er for layer 2 (fp16 feat2) ----------------
__global__ void elr2_kernel(const __half* __restrict__ feat2, const float* __restrict__ al,
                            const float* __restrict__ ar, float* __restrict__ el,
                            float* __restrict__ er, int M) {
    int warp = threadIdx.x >> 5, lane = threadIdx.x & 31;
    int n = blockIdx.x * 8 + warp;
    if (n >= M) return;
    int d0 = lane * 2;
    float2 f = __half22float2(*(const __half2*)(feat2 + (size_t)n * HF + d0));
    float pl = f.x * al[d0] + f.y * al[d0 + 1];
    float pr = f.x * ar[d0] + f.y * ar[d0 + 1];
#pragma unroll
    for (int o = 16; o > 0; o >>= 1) {
        pl += __shfl_xor_sync(0xffffffffu, pl, o);
        pr += __shfl_xor_sync(0xffffffffu, pr, o);
    }
    if (lane == 0) { el[n] = pl; er[n] = pr; }
}

// ---------------- layer-2 aggregation: one warp per node, batch-8 ----------------
__global__ void agg2_kernel(const __half* __restrict__ feat2, const float* __restrict__ el,
                            const float* __restrict__ er, const int* __restrict__ off,
                            const int* __restrict__ degv, const int* __restrict__ srcs,
                            const float* __restrict__ h1, const float* __restrict__ b2,
                            const int* __restrict__ gid, float* __restrict__ pool, int M) {
    int warp = threadIdx.x >> 5, lane = threadIdx.x & 31;
    int n = blockIdx.x * 8 + warp;
    if (n >= M) return;
    int d0 = lane * 2;
    int start = off[n];
    int deg = degv[n];
    float ern = er[n];

    float m = -1e30f, den = 0.f, a0 = 0.f, a1 = 0.f;

    for (int k0 = 0; k0 < deg; k0 += 8) {
        int cnt = deg - k0;
        int s8[8];
        s8[0] = srcs[start + k0];
#pragma unroll
        for (int i = 1; i < 8; i++)
            s8[i] = (i < cnt) ? srcs[start + k0 + i] : s8[0];
        float e8[8];
#pragma unroll
        for (int i = 0; i < 8; i++) e8[i] = el[s8[i]];
        unsigned f8[8];
#pragma unroll
        for (int i = 0; i < 8; i++)
            f8[i] = *(const unsigned*)(feat2 + (size_t)s8[i] * HF + d0);
        float bm = -1e30f;
#pragma unroll
        for (int i = 0; i < 8; i++) {
            float e = e8[i] + ern;
            e = e > 0.f ? e : 0.2f * e;
            e8[i] = (i < cnt) ? e : -1e30f;
            bm = fmaxf(bm, e8[i]);
        }
        if (bm > m) {
            float c = __expf(m - bm);
            den *= c; a0 *= c; a1 *= c;
            m = bm;
        }
#pragma unroll
        for (int i = 0; i < 8; i++) {
            float p = __expf(e8[i] - m);
            den += p;
            float2 v = __half22float2(*(const __half2*)&f8[i]);
            a0 += p * v.x;
            a1 += p * v.y;
        }
    }
    float inv = (deg > 0) ? (1.f / den) : 0.f;
    float2 hv = *(const float2*)(h1 + (size_t)n * HF + d0);
    float x0 = elu_fast(a0 * inv + hv.x + b2[d0]);
    float x1 = elu_fast(a1 * inv + hv.y + b2[d0 + 1]);
    float s1 = x0 + x1;
    float s2 = x0 * x0 + x1 * x1;
#pragma unroll
    for (int o = 16; o > 0; o >>= 1) {
        s1 += __shfl_xor_sync(0xffffffffu, s1, o);
        s2 += __shfl_xor_sync(0xffffffffu, s2, o);
    }
    float mu = s1 * (1.f / 64.f);
    float var = s2 * (1.f / 64.f) - mu * mu;
    float rs = rsqrtf(var + 1e-5f);
    float y0 = (x0 - mu) * rs;
    float y1 = (x1 - mu) * rs;
    int g = gid[n];
    atomicAdd(&pool[g * HF + d0 + 0], y0);
    atomicAdd(&pool[g * HF + d0 + 1], y1);
}

// ---------------- fused graph head ----------------
__global__ void head_kernel(const float* __restrict__ p0, const float* __restrict__ p1,
                            const float* __restrict__ p2, const float* __restrict__ gW1,
                            const float* __restrict__ gb1, const float* __restrict__ gW2,
                            const float* __restrict__ gb2, const float* __restrict__ mW0,
                            const float* __restrict__ mb0, const float* __restrict__ mW1,
                            const float* __restrict__ mb1, const float* __restrict__ mW2,
                            const float* __restrict__ mb2, float* __restrict__ out) {
    __shared__ float a1[64], a2[64], hg[64], t0s[256], t1s[256];
    int g = blockIdx.x, t = threadIdx.x;
    if (t < 64) { a1[t] = p1[g * 64 + t]; a2[t] = p2[g * 64 + t]; }
    __syncthreads();
    if (t < 64) {
        float s1 = gb1[t], s2 = gb2[t];
        for (int k = 0; k < 64; k++) {
            s1 += a1[k] * gW1[k * 64 + t];
            s2 += a2[k] * gW2[k * 64 + t];
        }
        s1 = s1 > 0.f ? s1 : 0.01f * s1;
        s2 = s2 > 0.f ? s2 : 0.01f * s2;
        hg[t] = p0[g * 64 + t] + s1 + s2;
    }
    __syncthreads();
    float acc = mb0[t];
    for (int k = 0; k < 64; k++) acc += hg[k] * mW0[k * 256 + t];
    t0s[t] = fmaxf(acc, 0.f);
    __syncthreads();
    acc = mb1[t];
    for (int k = 0; k < 256; k++) acc += t0s[k] * mW1[k * 256 + t];
    t1s[t] = fmaxf(acc, 0.f);
    __syncthreads();
    acc = mb2[t];
    for (int k = 0; k < 256; k++) acc += t1s[k] * mW2[k * 256 + t];
    out[g * 256 + t] = acc;
}

// ---------------- launch ----------------
extern "C" void kernel_launch(void* const* d_in, const int* in_sizes, int n_in,
                              void* d_out, int out_size) {
    const float* X     = (const float*)d_in[0];
    const int*   src   = (const int*)d_in[1];
    const int*   dst   = (const int*)d_in[2];
    const int*   gid   = (const int*)d_in[3];
    const float* projW = (const float*)d_in[4];
    const float* projb = (const float*)d_in[5];
    const float* fcW1  = (const float*)d_in[6];
    const float* al1   = (const float*)d_in[7];
    const float* ar1   = (const float*)d_in[8];
    const float* resW1 = (const float*)d_in[9];
    const float* b1    = (const float*)d_in[10];
    const float* fcW2  = (const float*)d_in[11];
    const float* al2   = (const float*)d_in[12];
    const float* ar2   = (const float*)d_in[13];
    const float* b2    = (const float*)d_in[14];
    const float* gW1   = (const float*)d_in[15];
    const float* gb1   = (const float*)d_in[16];
    const float* gW2   = (const float*)d_in[17];
    const float* gb2   = (const float*)d_in[18];
    const float* mW0   = (const float*)d_in[19];
    const float* mb0   = (const float*)d_in[20];
    const float* mW1   = (const float*)d_in[21];
    const float* mb1   = (const float*)d_in[22];
    const float* mW2   = (const float*)d_in[23];
    const float* mb2   = (const float*)d_in[24];

    int M = in_sizes[0] / HF;
    int E = in_sizes[1];

    float *h, *el1, *er1, *h1, *el2, *er2;
    float *p0, *p1, *p2;
    __half *feat1, *res1, *feat2;
    int *deg, *off, *cur, *bsum, *srcs;
    cudaGetSymbolAddress((void**)&h, g_h);
    cudaGetSymbolAddress((void**)&feat1, g_feat1);
    cudaGetSymbolAddress((void**)&res1, g_res1);
    cudaGetSymbolAddress((void**)&el1, g_el1);
    cudaGetSymbolAddress((void**)&er1, g_er1);
    cudaGetSymbolAddress((void**)&h1, g_h1);
    cudaGetSymbolAddress((void**)&feat2, g_feat2);
    cudaGetSymbolAddress((void**)&el2, g_el2);
    cudaGetSymbolAddress((void**)&er2, g_er2);
    cudaGetSymbolAddress((void**)&deg, g_deg);
    cudaGetSymbolAddress((void**)&off, g_off);
    cudaGetSymbolAddress((void**)&cur, g_cur);
    cudaGetSymbolAddress((void**)&bsum, g_bsum);
    cudaGetSymbolAddress((void**)&srcs, g_srcs);
    cudaGetSymbolAddress((void**)&p0, g_p0);
    cudaGetSymbolAddress((void**)&p1, g_p1);
    cudaGetSymbolAddress((void**)&p2, g_p2);

    static int smem_set = 0;
    if (!smem_set) {
        cudaFuncSetAttribute(gemm_tf32, cudaFuncAttributeMaxDynamicSharedMemorySize,
                             GEMM_SMEM);
        cudaFuncSetAttribute(gemm_fr1, cudaFuncAttributeMaxDynamicSharedMemorySize,
                             GEMM_SMEM_FR);
        smem_set = 1;
    }

    int nwb = (M + 7) / 8;
    int nwb2 = (M + 1) / 2;
    int rowTiles = (M + 127) / 128;
    int scanBlocks = (M + 255) / 256;

    init_kernel<<<(M + 255) / 256, 256>>>(deg, p0, p1, p2, M);                        // 1
    hist_kernel<<<(E + 255) / 256, 256>>>(dst, deg, E);                               // 2
    gemm_tf32<<<dim3(1, rowTiles), 256, GEMM_SMEM>>>(X, projW, HF, HF, h, nullptr,
                                                     HF, M, projb, gid, p0);          // 3
    gemm_fr1<<<dim3(8, rowTiles), 256, GEMM_SMEM_FR>>>(h, fcW1, resW1, feat1, res1,
                                                       al1, ar1, el1, er1, M);        // 4 <- capture
    scan1_kernel<<<scanBlocks, 256>>>(deg, off, bsum, M);                             // 5
    scan2_kernel<<<scanBlocks, 256>>>(bsum, off, cur, M, scanBlocks);                 // 6
    scatter_kernel<<<(E + 255) / 256, 256>>>(src, dst, cur, srcs, E);                 // 7
    agg1_kernel<<<nwb2, 256>>>(feat1, res1, el1, er1, off, deg, srcs, b1, gid,
                               h1, p1, M);                                            // 8
    gemm_tf32<<<dim3(1, rowTiles), 256, GEMM_SMEM>>>(h1, fcW2, HF, HF, nullptr,
                                                     feat2, HF, M, nullptr, nullptr,
                                                     nullptr);                        // 9
    elr2_kernel<<<nwb, 256>>>(feat2, al2, ar2, el2, er2, M);                          // 10
    agg2_kernel<<<nwb, 256>>>(feat2, el2, er2, off, deg, srcs, h1, b2, gid, p2, M);   // 11
    head_kernel<<<GG, MLPD>>>(p0, p1, p2, gW1, gb1, gW2, gb2, mW0, mb0, mW1, mb1,
                              mW2, mb2, (float*)d_out);                               // 12
}

// round 16
// speedup vs baseline: 1.1391x; 1.0267x over previous
#include <cuda_runtime.h>
#include <cuda_fp16.h>
#include <math.h>

#define NN 30000
#define EE 480000
#define GG 64
#define HF 64
#define HEADS 8
#define MLPD 256

// ---------------- device scratch ----------------
__device__ float  g_h[NN * HF];
__device__ __half g_feat1[(size_t)NN * 512];
__device__ __half g_res1[(size_t)NN * 512];
__device__ float  g_el1[NN * HEADS];
__device__ float  g_er1[NN * HEADS];
__device__ float  g_h1[NN * HF];
__device__ __half g_feat2[NN * HF];
__device__ float  g_el2[NN];
__device__ float  g_er2[NN];
__device__ int    g_deg[NN];
__device__ int    g_off[NN];
__device__ int    g_cur[NN];
__device__ int    g_bsum[256];
__device__ int    g_srcs[EE];
__device__ float  g_p0[GG * HF];
__device__ float  g_p1[GG * HF];
__device__ float  g_p2[GG * HF];

// ---------------- helpers ----------------
__device__ __forceinline__ void mma_f16(float* c, unsigned a0, unsigned a1,
                                        unsigned a2, unsigned a3,
                                        unsigned b0, unsigned b1) {
    asm("mma.sync.aligned.m16n8k16.row.col.f32.f16.f16.f32 "
        "{%0,%1,%2,%3},{%4,%5,%6,%7},{%8,%9},{%0,%1,%2,%3};"
        : "+f"(c[0]), "+f"(c[1]), "+f"(c[2]), "+f"(c[3])
        : "r"(a0), "r"(a1), "r"(a2), "r"(a3), "r"(b0), "r"(b1));
}

__device__ __forceinline__ float elu_fast(float x) {
    return x > 0.f ? x : (__expf(x) - 1.f);
}

// ---------------- init ----------------
__global__ void init_kernel(int* deg, float* p0, float* p1, float* p2, int n) {
    int i = blockIdx.x * blockDim.x + threadIdx.x;
    if (i < n) deg[i] = 0;
    if (i < GG * HF) { p0[i] = 0.f; p1[i] = 0.f; p2[i] = 0.f; }
}

// ---------------- CSR build ----------------
__global__ void hist_kernel(const int* __restrict__ dst, int* __restrict__ deg, int E) {
    int e = blockIdx.x * blockDim.x + threadIdx.x;
    if (e < E) atomicAdd(&deg[dst[e]], 1);
}

__global__ void scan1_kernel(const int* __restrict__ deg, int* __restrict__ off,
                             int* __restrict__ bsum, int n) {
    __shared__ int sm[256];
    int t = threadIdx.x;
    int i = blockIdx.x * 256 + t;
    int v = (i < n) ? deg[i] : 0;
    sm[t] = v;
    __syncthreads();
#pragma unroll
    for (int o = 1; o < 256; o <<= 1) {
        int x = (t >= o) ? sm[t - o] : 0;
        __syncthreads();
        sm[t] += x;
        __syncthreads();
    }
    if (i < n) off[i] = sm[t] - v;
    if (t == 255) bsum[blockIdx.x] = sm[255];
}

__global__ void scan2_kernel(const int* __restrict__ bsum, int* __restrict__ off,
                             int* __restrict__ cur, int n, int nblocks) {
    __shared__ int sb[256];
    int t = threadIdx.x;
    sb[t] = (t < nblocks) ? bsum[t] : 0;
    __syncthreads();
#pragma unroll
    for (int o = 1; o < 256; o <<= 1) {
        int x = (t >= o) ? sb[t - o] : 0;
        __syncthreads();
        sb[t] += x;
        __syncthreads();
    }
    int b = blockIdx.x;
    int base = (b > 0) ? sb[b - 1] : 0;
    int i = b * 256 + t;
    if (i < n) {
        int o = off[i] + base;
        off[i] = o;
        cur[i] = o;
    }
}

__global__ void scatter_kernel(const int* __restrict__ src, const int* __restrict__ dst,
                               int* __restrict__ cur, int* __restrict__ srcs, int E) {
    int e = blockIdx.x * blockDim.x + threadIdx.x;
    if (e < E) {
        int d = dst[e];
        int pos = atomicAdd(&cur[d], 1);
        srcs[pos] = src[e];
    }
}

// ---------------- fp16 HMMA GEMMs (m16n8k16, fp32 accum) ----------------
// A smem: halves, fragment-major per row: offset(k) = (k>>4)*16 + (((k&15)>>1)&3)*4
//         + ((k>>3)&1)*2 + (k&1); row pitch AS_LDU=36 uints (72 halves).
// B smem: half2 rows kp=k/2 (32 rows), pitch WS_LDU=136 uints; fragment = 1 LDS.32.
#define AS_LDU 36
#define WS_LDU 136
#define GEMM_SMEM ((128 * AS_LDU + 32 * WS_LDU) * 4)
#define GEMM_SMEM_FR (GEMM_SMEM + 256 * 4)

__device__ __forceinline__ void load_A_tile(const float* __restrict__ A, unsigned* As,
                                            int r0, int M, int tid) {
    __half* Ah = (__half*)As;
#pragma unroll
    for (int i = 0; i < 8; i++) {
        int f = tid + i * 256;
        int row = f >> 4;
        int c4 = (f & 15) * 4;
        float4 v = make_float4(0.f, 0.f, 0.f, 0.f);
        if (r0 + row < M) v = *(const float4*)(A + (size_t)(r0 + row) * 64 + c4);
        const float* vp = &v.x;
#pragma unroll
        for (int j = 0; j < 4; j++) {
            int k = c4 + j;
            int off = (k >> 4) * 16 + (((k & 15) >> 1) & 3) * 4 + ((k >> 3) & 1) * 2 + (k & 1);
            Ah[row * (AS_LDU * 2) + off] = __float2half_rn(vp[j]);
        }
    }
}

__device__ __forceinline__ void load_W_tile(const float* __restrict__ W, unsigned* Ws,
                                            int ldw, int NC, int c0, int tid) {
    __half* Wh = (__half*)Ws;
#pragma unroll
    for (int i = 0; i < 8; i++) {
        int f = tid + i * 256;
        int row = f >> 5;           // k 0..63
        int c4 = (f & 31) * 4;
        float4 v = make_float4(0.f, 0.f, 0.f, 0.f);
        if (c0 + c4 < NC) v = *(const float4*)(W + (size_t)row * ldw + c0 + c4);
        int kp = row >> 1;
        int par = row & 1;
        const float* vp = &v.x;
#pragma unroll
        for (int j = 0; j < 4; j++)
            Wh[(kp * WS_LDU + c4 + j) * 2 + par] = __float2half_rn(vp[j]);
    }
}

__device__ __forceinline__ void gemm_mainloop(const unsigned* As, const unsigned* Ws,
                                              float acc[2][8][4], int wm, int wn,
                                              int g, int tg) {
#pragma unroll
    for (int kb = 0; kb < 4; kb++) {
        unsigned a[2][4];
#pragma unroll
        for (int mt = 0; mt < 2; mt++) {
            int rb = wm * 32 + mt * 16;
            uint2 pa = *(const uint2*)&As[(rb + g) * AS_LDU + kb * 8 + tg * 2];
            uint2 pb = *(const uint2*)&As[(rb + 8 + g) * AS_LDU + kb * 8 + tg * 2];
            a[mt][0] = pa.x; a[mt][2] = pa.y;
            a[mt][1] = pb.x; a[mt][3] = pb.y;
        }
        const unsigned* w0 = Ws + (kb * 8 + tg) * WS_LDU;
        const unsigned* w1 = Ws + (kb * 8 + tg + 4) * WS_LDU;
#pragma unroll
        for (int nt = 0; nt < 8; nt++) {
            int cb = wn * 64 + nt * 8 + g;
            unsigned b0 = w0[cb];
            unsigned b1 = w1[cb];
            mma_f16(acc[0][nt], a[0][0], a[0][1], a[0][2], a[0][3], b0, b1);
            mma_f16(acc[1][nt], a[1][0], a[1][1], a[1][2], a[1][3], b0, b1);
        }
    }
}

__global__ void gemm_f16(const float* __restrict__ A, const float* __restrict__ W,
                         int ldw, int NC, float* __restrict__ C, __half* __restrict__ Ch,
                         int ldc, int M, const float* __restrict__ bias,
                         const int* __restrict__ gid, float* __restrict__ pool) {
    extern __shared__ unsigned smem_u[];
    unsigned* As = smem_u;
    unsigned* Ws = smem_u + 128 * AS_LDU;
    int tid = threadIdx.x;
    int warp = tid >> 5, lane = tid & 31;
    int g = lane >> 2, tg = lane & 3;
    int wm = warp & 3, wn = warp >> 2;
    int r0 = blockIdx.y * 128;
    int c0 = blockIdx.x * 128;

    load_A_tile(A, As, r0, M, tid);
    load_W_tile(W, Ws, ldw, NC, c0, tid);
    __syncthreads();

    float acc[2][8][4];
#pragma unroll
    for (int mt = 0; mt < 2; mt++)
#pragma unroll
        for (int nt = 0; nt < 8; nt++)
#pragma unroll
            for (int q = 0; q < 4; q++) acc[mt][nt][q] = 0.f;

    gemm_mainloop(As, Ws, acc, wm, wn, g, tg);

#pragma unroll
    for (int mt = 0; mt < 2; mt++) {
#pragma unroll
        for (int nt = 0; nt < 8; nt++) {
            int col = c0 + wn * 64 + nt * 8 + tg * 2;
            if (col >= NC) continue;
            float bv0 = 0.f, bv1 = 0.f;
            if (bias) { bv0 = bias[col]; bv1 = bias[col + 1]; }
            int rowA = r0 + wm * 32 + mt * 16 + g;
#pragma unroll
            for (int half = 0; half < 2; half++) {
                int row = rowA + half * 8;
                if (row >= M) continue;
                float v0 = acc[mt][nt][half * 2 + 0] + bv0;
                float v1 = acc[mt][nt][half * 2 + 1] + bv1;
                if (Ch) {
                    *(__half2*)(Ch + (size_t)row * ldc + col) = __floats2half2_rn(v0, v1);
                } else {
                    *(float2*)(C + (size_t)row * ldc + col) = make_float2(v0, v1);
                    if (pool) {
                        int gi = gid[row];
                        atomicAdd(&pool[gi * HF + col], v0);
                        atomicAdd(&pool[gi * HF + col + 1], v1);
                    }
                }
            }
        }
    }
}

// fused fc1+res1 with el1/er1 computed in the epilogue of feat blocks.
__global__ void gemm_fr1(const float* __restrict__ A, const float* __restrict__ Wf,
                         const float* __restrict__ Wr, __half* __restrict__ feat1,
                         __half* __restrict__ res1, const float* __restrict__ al1,
                         const float* __restrict__ ar1, float* __restrict__ el,
                         float* __restrict__ er, int M) {
    extern __shared__ unsigned smem_u[];
    unsigned* As = smem_u;
    unsigned* Ws = smem_u + 128 * AS_LDU;
    float* al_s = (float*)(smem_u + 128 * AS_LDU + 32 * WS_LDU);
    float* ar_s = al_s + 128;
    int tid = threadIdx.x;
    int warp = tid >> 5, lane = tid & 31;
    int g = lane >> 2, tg = lane & 3;
    int wm = warp & 3, wn = warp >> 2;
    int r0 = blockIdx.y * 128;
    int bx = blockIdx.x;
    int c0 = (bx & 3) * 128;
    bool isFeat = (bx < 4);
    const float* W = isFeat ? Wf : Wr;
    __half* Out = isFeat ? feat1 : res1;

    load_A_tile(A, As, r0, M, tid);
    load_W_tile(W, Ws, 512, 512, c0, tid);
    if (isFeat && tid < 128) {
        al_s[tid] = al1[c0 + tid];
        ar_s[tid] = ar1[c0 + tid];
    }
    __syncthreads();

    float acc[2][8][4];
#pragma unroll
    for (int mt = 0; mt < 2; mt++)
#pragma unroll
        for (int nt = 0; nt < 8; nt++)
#pragma unroll
            for (int q = 0; q < 4; q++) acc[mt][nt][q] = 0.f;

    gemm_mainloop(As, Ws, acc, wm, wn, g, tg);

    float pl[2][2] = {{0.f, 0.f}, {0.f, 0.f}};
    float pr[2][2] = {{0.f, 0.f}, {0.f, 0.f}};

#pragma unroll
    for (int mt = 0; mt < 2; mt++) {
#pragma unroll
        for (int nt = 0; nt < 8; nt++) {
            int lcol = wn * 64 + nt * 8 + tg * 2;
            int col = c0 + lcol;
            int rowA = r0 + wm * 32 + mt * 16 + g;
            float a0 = 0.f, a1 = 0.f, b0 = 0.f, b1 = 0.f;
            if (isFeat) {
                a0 = al_s[lcol]; a1 = al_s[lcol + 1];
                b0 = ar_s[lcol]; b1 = ar_s[lcol + 1];
            }
#pragma unroll
            for (int half = 0; half < 2; half++) {
                int row = rowA + half * 8;
                if (row >= M) continue;
                float v0 = acc[mt][nt][half * 2 + 0];
                float v1 = acc[mt][nt][half * 2 + 1];
                *(__half2*)(Out + (size_t)row * 512 + col) = __floats2half2_rn(v0, v1);
                if (isFeat) {
                    pl[mt][half] += v0 * a0 + v1 * a1;
                    pr[mt][half] += v0 * b0 + v1 * b1;
                }
            }
        }
    }

    if (isFeat) {
        int head = 2 * (bx & 3) + wn;
#pragma unroll
        for (int mt = 0; mt < 2; mt++) {
#pragma unroll
            for (int half = 0; half < 2; half++) {
                float l = pl[mt][half];
                float r = pr[mt][half];
                l += __shfl_xor_sync(0xffffffffu, l, 1);
                l += __shfl_xor_sync(0xffffffffu, l, 2);
                r += __shfl_xor_sync(0xffffffffu, r, 1);
                r += __shfl_xor_sync(0xffffffffu, r, 2);
                int row = r0 + wm * 32 + mt * 16 + g + half * 8;
                if (tg == 0 && row < M) {
                    el[row * HEADS + head] = l;
                    er[row * HEADS + head] = r;
                }
            }
        }
    }
}

// ---------------- layer-1 aggregation: 4 warps per node (2 heads/warp) -------------
__global__ void agg1_kernel(const __half* __restrict__ feat1, const __half* __restrict__ res1,
                            const float* __restrict__ el, const float* __restrict__ er,
                            const int* __restrict__ off, const int* __restrict__ degv,
                            const int* __restrict__ srcs, const float* __restrict__ b1,
                            const int* __restrict__ gid, float* __restrict__ h1,
                            float* __restrict__ pool, int M) {
    __shared__ float sy[2][512];
    int warp = threadIdx.x >> 5, lane = threadIdx.x & 31;
    int nid = warp >> 2;
    int wn = warp & 3;
    int n = blockIdx.x * 2 + nid;
    bool active = (n < M);
    int hh = wn * 2 + (lane >> 4);
    int p = lane & 15;
    int col = hh * 64 + p * 4;

    int start = 0, deg = 0;
    float erh = 0.f;
    if (active) {
        start = off[n];
        deg = degv[n];
        erh = er[n * HEADS + hh];
    }

    float m = -1e30f, den = 0.f;
    float acc[4] = {0.f, 0.f, 0.f, 0.f};

    for (int k0 = 0; k0 < deg; k0 += 4) {
        int cnt = deg - k0;
        int s4[4];
        s4[0] = srcs[start + k0];
#pragma unroll
        for (int i = 1; i < 4; i++)
            s4[i] = (i < cnt) ? srcs[start + k0 + i] : s4[0];
        float e4[4];
#pragma unroll
        for (int i = 0; i < 4; i++) e4[i] = el[s4[i] * HEADS + hh];
        uint2 f4[4];
#pragma unroll
        for (int i = 0; i < 4; i++)
            f4[i] = *(const uint2*)(feat1 + (size_t)s4[i] * 512 + col);
        float bm = -1e30f;
#pragma unroll
        for (int i = 0; i < 4; i++) {
            float e = e4[i] + erh;
            e = e > 0.f ? e : 0.2f * e;
            e4[i] = (i < cnt) ? e : -1e30f;
            bm = fmaxf(bm, e4[i]);
        }
        if (bm > m) {
            float c = __expf(m - bm);
            den *= c;
#pragma unroll
            for (int q = 0; q < 4; q++) acc[q] *= c;
            m = bm;
        }
#pragma unroll
        for (int i = 0; i < 4; i++) {
            float pw = __expf(e4[i] - m);
            den += pw;
            __half2 lo = *(__half2*)&f4[i].x;
            __half2 hi = *(__half2*)&f4[i].y;
            float2 v0 = __half22float2(lo);
            float2 v1 = __half22float2(hi);
            acc[0] += pw * v0.x;
            acc[1] += pw * v0.y;
            acc[2] += pw * v1.x;
            acc[3] += pw * v1.y;
        }
    }
    float inv = (deg > 0) ? (1.f / den) : 0.f;

    float x[4] = {0.f, 0.f, 0.f, 0.f};
    float s1 = 0.f, s2 = 0.f;
    if (active) {
        uint2 rv = *(const uint2*)(res1 + (size_t)n * 512 + col);
        __half2 rlo = *(__half2*)&rv.x;
        __half2 rhi = *(__half2*)&rv.y;
        float2 r0 = __half22float2(rlo);
        float2 r1 = __half22float2(rhi);
        float rr[4] = {r0.x, r0.y, r1.x, r1.y};
        float4 bv = *(const float4*)(b1 + col);
        float bb[4] = {bv.x, bv.y, bv.z, bv.w};
#pragma unroll
        for (int q = 0; q < 4; q++) {
            float val = acc[q] * inv + rr[q] + bb[q];
            val = elu_fast(val);
            x[q] = val;
            s1 += val;
            s2 += val * val;
        }
    }
#pragma unroll
    for (int o = 1; o <= 8; o <<= 1) {
        s1 += __shfl_xor_sync(0xffffffffu, s1, o);
        s2 += __shfl_xor_sync(0xffffffffu, s2, o);
    }
    float mu = s1 * (1.f / 64.f);
    float var = s2 * (1.f / 64.f) - mu * mu;
    float rs = rsqrtf(var + 1e-5f);
    if (active) {
#pragma unroll
        for (int q = 0; q < 4; q++)
            sy[nid][col + q] = (x[q] - mu) * rs;
    }
    __syncthreads();
    if (wn == 0 && active) {
        int d0 = lane * 2;
        float y0 = 0.f, y1 = 0.f;
#pragma unroll
        for (int hq = 0; hq < 8; hq++) {
            y0 += sy[nid][hq * 64 + d0];
            y1 += sy[nid][hq * 64 + d0 + 1];
        }
        y0 *= 0.125f;
        y1 *= 0.125f;
        int g = gid[n];
        *(float2*)(h1 + (size_t)n * HF + d0) = make_float2(y0, y1);
        atomicAdd(&pool[g * HF + d0 + 0], y0);
        atomicAdd(&pool[g * HF + d0 + 1], y1);
    }
}

// ---------------- el/er for layer 2 (fp16 feat2) ----------------
__global__ void elr2_kernel(const __half* __restrict__ feat2, const float* __restrict__ al,
                            const float* __restrict__ ar, float* __restrict__ el,
                            float* __restrict__ er, int M) {
    int warp = threadIdx.x >> 5, lane = threadIdx.x & 31;
    int n = blockIdx.x * 8 + warp;
    if (n >= M) return;
    int d0 = lane * 2;
    float2 f = __half22float2(*(const __half2*)(feat2 + (size_t)n * HF + d0));
    float pl = f.x * al[d0] + f.y * al[d0 + 1];
    float pr = f.x * ar[d0] + f.y * ar[d0 + 1];
#pragma unroll
    for (int o = 16; o > 0; o >>= 1) {
        pl += __shfl_xor_sync(0xffffffffu, pl, o);
        pr += __shfl_xor_sync(0xffffffffu, pr, o);
    }
    if (lane == 0) { el[n] = pl; er[n] = pr; }
}

// ---------------- layer-2 aggregation: one warp per node, batch-8 ----------------
__global__ void agg2_kernel(const __half* __restrict__ feat2, const float* __restrict__ el,
                            const float* __restrict__ er, const int* __restrict__ off,
                            const int* __restrict__ degv, const int* __restrict__ srcs,
                            const float* __restrict__ h1, const float* __restrict__ b2,
                            const int* __restrict__ gid, float* __restrict__ pool, int M) {
    int warp = threadIdx.x >> 5, lane = threadIdx.x & 31;
    int n = blockIdx.x * 8 + warp;
    if (n >= M) return;
    int d0 = lane * 2;
    int start = off[n];
    int deg = degv[n];
    float ern = er[n];

    float m = -1e30f, den = 0.f, a0 = 0.f, a1 = 0.f;

    for (int k0 = 0; k0 < deg; k0 += 8) {
        int cnt = deg - k0;
        int s8[8];
        s8[0] = srcs[start + k0];
#pragma unroll
        for (int i = 1; i < 8; i++)
            s8[i] = (i < cnt) ? srcs[start + k0 + i] : s8[0];
        float e8[8];
#pragma unroll
        for (int i = 0; i < 8; i++) e8[i] = el[s8[i]];
        unsigned f8[8];
#pragma unroll
        for (int i = 0; i < 8; i++)
            f8[i] = *(const unsigned*)(feat2 + (size_t)s8[i] * HF + d0);
        float bm = -1e30f;
#pragma unroll
        for (int i = 0; i < 8; i++) {
            float e = e8[i] + ern;
            e = e > 0.f ? e : 0.2f * e;
            e8[i] = (i < cnt) ? e : -1e30f;
            bm = fmaxf(bm, e8[i]);
        }
        if (bm > m) {
            float c = __expf(m - bm);
            den *= c; a0 *= c; a1 *= c;
            m = bm;
        }
#pragma unroll
        for (int i = 0; i < 8; i++) {
            float p = __expf(e8[i] - m);
            den += p;
            float2 v = __half22float2(*(const __half2*)&f8[i]);
            a0 += p * v.x;
            a1 += p * v.y;
        }
    }
    float inv = (deg > 0) ? (1.f / den) : 0.f;
    float2 hv = *(const float2*)(h1 + (size_t)n * HF + d0);
    float x0 = elu_fast(a0 * inv + hv.x + b2[d0]);
    float x1 = elu_fast(a1 * inv + hv.y + b2[d0 + 1]);
    float s1 = x0 + x1;
    float s2 = x0 * x0 + x1 * x1;
#pragma unroll
    for (int o = 16; o > 0; o >>= 1) {
        s1 += __shfl_xor_sync(0xffffffffu, s1, o);
        s2 += __shfl_xor_sync(0xffffffffu, s2, o);
    }
    float mu = s1 * (1.f / 64.f);
    float var = s2 * (1.f / 64.f) - mu * mu;
    float rs = rsqrtf(var + 1e-5f);
    float y0 = (x0 - mu) * rs;
    float y1 = (x1 - mu) * rs;
    int g = gid[n];
    atomicAdd(&pool[g * HF + d0 + 0], y0);
    atomicAdd(&pool[g * HF + d0 + 1], y1);
}

// ---------------- fused graph head ----------------
__global__ void head_kernel(const float* __restrict__ p0, const float* __restrict__ p1,
                            const float* __restrict__ p2, const float* __restrict__ gW1,
                            const float* __restrict__ gb1, const float* __restrict__ gW2,
                            const float* __restrict__ gb2, const float* __restrict__ mW0,
                            const float* __restrict__ mb0, const float* __restrict__ mW1,
                            const float* __restrict__ mb1, const float* __restrict__ mW2,
                            const float* __restrict__ mb2, float* __restrict__ out) {
    __shared__ float a1[64], a2[64], hg[64], t0s[256], t1s[256];
    int g = blockIdx.x, t = threadIdx.x;
    if (t < 64) { a1[t] = p1[g * 64 + t]; a2[t] = p2[g * 64 + t]; }
    __syncthreads();
    if (t < 64) {
        float s1 = gb1[t], s2 = gb2[t];
        for (int k = 0; k < 64; k++) {
            s1 += a1[k] * gW1[k * 64 + t];
            s2 += a2[k] * gW2[k * 64 + t];
        }
        s1 = s1 > 0.f ? s1 : 0.01f * s1;
        s2 = s2 > 0.f ? s2 : 0.01f * s2;
        hg[t] = p0[g * 64 + t] + s1 + s2;
    }
    __syncthreads();
    float acc = mb0[t];
    for (int k = 0; k < 64; k++) acc += hg[k] * mW0[k * 256 + t];
    t0s[t] = fmaxf(acc, 0.f);
    __syncthreads();
    acc = mb1[t];
    for (int k = 0; k < 256; k++) acc += t0s[k] * mW1[k * 256 + t];
    t1s[t] = fmaxf(acc, 0.f);
    __syncthreads();
    acc = mb2[t];
    for (int k = 0; k < 256; k++) acc += t1s[k] * mW2[k * 256 + t];
    out[g * 256 + t] = acc;
}

// ---------------- launch ----------------
extern "C" void kernel_launch(void* const* d_in, const int* in_sizes, int n_in,
                              void* d_out, int out_size) {
    const float* X     = (const float*)d_in[0];
    const int*   src   = (const int*)d_in[1];
    const int*   dst   = (const int*)d_in[2];
    const int*   gid   = (const int*)d_in[3];
    const float* projW = (const float*)d_in[4];
    const float* projb = (const float*)d_in[5];
    const float* fcW1  = (const float*)d_in[6];
    const float* al1   = (const float*)d_in[7];
    const float* ar1   = (const float*)d_in[8];
    const float* resW1 = (const float*)d_in[9];
    const float* b1    = (const float*)d_in[10];
    const float* fcW2  = (const float*)d_in[11];
    const float* al2   = (const float*)d_in[12];
    const float* ar2   = (const float*)d_in[13];
    const float* b2    = (const float*)d_in[14];
    const float* gW1   = (const float*)d_in[15];
    const float* gb1   = (const float*)d_in[16];
    const float* gW2   = (const float*)d_in[17];
    const float* gb2   = (const float*)d_in[18];
    const float* mW0   = (const float*)d_in[19];
    const float* mb0   = (const float*)d_in[20];
    const float* mW1   = (const float*)d_in[21];
    const float* mb1   = (const float*)d_in[22];
    const float* mW2   = (const float*)d_in[23];
    const float* mb2   = (const float*)d_in[24];

    int M = in_sizes[0] / HF;
    int E = in_sizes[1];

    float *h, *el1, *er1, *h1, *el2, *er2;
    float *p0, *p1, *p2;
    __half *feat1, *res1, *feat2;
    int *deg, *off, *cur, *bsum, *srcs;
    cudaGetSymbolAddress((void**)&h, g_h);
    cudaGetSymbolAddress((void**)&feat1, g_feat1);
    cudaGetSymbolAddress((void**)&res1, g_res1);
    cudaGetSymbolAddress((void**)&el1, g_el1);
    cudaGetSymbolAddress((void**)&er1, g_er1);
    cudaGetSymbolAddress((void**)&h1, g_h1);
    cudaGetSymbolAddress((void**)&feat2, g_feat2);
    cudaGetSymbolAddress((void**)&el2, g_el2);
    cudaGetSymbolAddress((void**)&er2, g_er2);
    cudaGetSymbolAddress((void**)&deg, g_deg);
    cudaGetSymbolAddress((void**)&off, g_off);
    cudaGetSymbolAddress((void**)&cur, g_cur);
    cudaGetSymbolAddress((void**)&bsum, g_bsum);
    cudaGetSymbolAddress((void**)&srcs, g_srcs);
    cudaGetSymbolAddress((void**)&p0, g_p0);
    cudaGetSymbolAddress((void**)&p1, g_p1);
    cudaGetSymbolAddress((void**)&p2, g_p2);

    static int smem_set = 0;
    if (!smem_set) {
        cudaFuncSetAttribute(gemm_f16, cudaFuncAttributeMaxDynamicSharedMemorySize,
                             GEMM_SMEM);
        cudaFuncSetAttribute(gemm_fr1, cudaFuncAttributeMaxDynamicSharedMemorySize,
                             GEMM_SMEM_FR);
        smem_set = 1;
    }

    int nwb = (M + 7) / 8;
    int nwb2 = (M + 1) / 2;
    int rowTiles = (M + 127) / 128;
    int scanBlocks = (M + 255) / 256;

    init_kernel<<<(M + 255) / 256, 256>>>(deg, p0, p1, p2, M);                        // 1
    hist_kernel<<<(E + 255) / 256, 256>>>(dst, deg, E);                               // 2
    gemm_f16<<<dim3(1, rowTiles), 256, GEMM_SMEM>>>(X, projW, HF, HF, h, nullptr,
                                                    HF, M, projb, gid, p0);           // 3
    gemm_fr1<<<dim3(8, rowTiles), 256, GEMM_SMEM_FR>>>(h, fcW1, resW1, feat1, res1,
                                                       al1, ar1, el1, er1, M);        // 4 <- capture
    scan1_kernel<<<scanBlocks, 256>>>(deg, off, bsum, M);                             // 5
    scan2_kernel<<<scanBlocks, 256>>>(bsum, off, cur, M, scanBlocks);                 // 6
    scatter_kernel<<<(E + 255) / 256, 256>>>(src, dst, cur, srcs, E);                 // 7
    agg1_kernel<<<nwb2, 256>>>(feat1, res1, el1, er1, off, deg, srcs, b1, gid,
                               h1, p1, M);                                            // 8
    gemm_f16<<<dim3(1, rowTiles), 256, GEMM_SMEM>>>(h1, fcW2, HF, HF, nullptr,
                                                    feat2, HF, M, nullptr, nullptr,
                                                    nullptr);                         // 9
    elr2_kernel<<<nwb, 256>>>(feat2, al2, ar2, el2, er2, M);                          // 10
    agg2_kernel<<<nwb, 256>>>(feat2, el2, er2, off, deg, srcs, h1, b2, gid, p2, M);   // 11
    head_kernel<<<GG, MLPD>>>(p0, p1, p2, gW1, gb1, gW2, gb2, mW0, mb0, mW1, mb1,
                              mW2, mb2, (float*)d_out);                               // 12
}